// round 1
// baseline (speedup 1.0000x reference)
#include <cuda_runtime.h>
#include <math.h>

#define BB 8
#define FR 257
#define TT 300
#define CC 64
#define CPP 16
#define NN (BB*TT)              /* 2400 */
#define NF ((size_t)NN*FR)      /* 616800 */
#define LN_EPS 1e-5f

// Scratch (device globals: allocation-free per harness rules)
__device__ float g_x1[(size_t)NN*FR*CC];   // stage-1 output  [n][f][c]
__device__ float g_hp[(size_t)CPP*NN*FR];  // reduced hidden  [p][n][f]
__device__ float g_hq[(size_t)NN*FR*CPP];  // fW GEMM output  [n][f][p]

// Load one 8-wide group row of ys (zero-padded outside [0,FR)) into regs.
#define LDROW(F, R) { \
  if ((unsigned)(F) < (unsigned)FR) { \
    float4 _a = *(const float4*)(ys + (F)*64 + gb); \
    float4 _b = *(const float4*)(ys + (F)*64 + gb + 4); \
    (R)[0]=_a.x;(R)[1]=_a.y;(R)[2]=_a.z;(R)[3]=_a.w; \
    (R)[4]=_b.x;(R)[5]=_b.y;(R)[6]=_b.z;(R)[7]=_b.w; \
  } else { \
    _Pragma("unroll") for (int _j=0;_j<8;_j++) (R)[_j]=0.f; \
  } }

#define WRED2(S,Q) { _Pragma("unroll") for (int _o=16;_o;_o>>=1){ \
  (S) += __shfl_xor_sync(0xffffffffu,(S),_o); \
  (Q) += __shfl_xor_sync(0xffffffffu,(Q),_o);} }

// ---------------------------------------------------------------------------
// K1: freq_conv #1 + LN2 + reduce-to-CPP   (one CTA per n)
// ---------------------------------------------------------------------------
__global__ __launch_bounds__(512) void k_freq1(
    const float* __restrict__ h,
    const float* __restrict__ g1, const float* __restrict__ b1,
    const float* __restrict__ w1, const float* __restrict__ cb1,
    const float* __restrict__ a1,
    const float* __restrict__ fg, const float* __restrict__ fbv,
    const float* __restrict__ rw_, const float* __restrict__ rb_)
{
  extern __shared__ float sm[];
  float* xs  = sm;                 // [FR*64]
  float* ys  = xs + FR*CC;         // [FR*64]  (reused as hp staging later)
  float* wc  = ys + FR*CC;         // [24*64]  layout [(k*8+ci)][c]
  float* rw  = wc + 24*CC;         // [16*64]  layout [p][c]
  float* par = rw + CPP*CC;        // g1|b1|cb|fg|fb (64 each) + rb(16)

  const int tid = threadIdx.x;
  const int n = blockIdx.x;
  const int b = n / TT, t = n % TT;

  if (tid < CC) {
    par[tid]     = g1[tid];  par[64+tid]  = b1[tid];  par[128+tid] = cb1[tid];
    par[192+tid] = fg[tid];  par[256+tid] = fbv[tid];
  }
  if (tid >= 64 && tid < 64+CPP) par[320 + (tid-64)] = rb_[tid-64];
  for (int i = tid; i < 24*CC; i += 512) {
    int c = i & 63, kk = i >> 6, k = kk >> 3, ci = kk & 7;
    wc[i] = w1[c*24 + ci*3 + k];
  }
  for (int i = tid; i < CPP*CC; i += 512) rw[i] = rw_[i];

  const float alpha = __ldg(a1);
  const float* hbase = h + ((size_t)b*FR*TT + t)*CC;
  float4* xs4 = (float4*)xs;
  for (int i = tid; i < FR*16; i += 512) {
    int f = i >> 4, q = i & 15;
    xs4[i] = ((const float4*)(hbase + (size_t)f*TT*CC))[q];
  }
  __syncthreads();

  const int wid = tid >> 5, lane = tid & 31;
  // LN1 -> ys
  for (int f = wid; f < FR; f += 16) {
    float v0 = xs[f*64+lane], v1 = xs[f*64+lane+32];
    float s = v0+v1, q = v0*v0+v1*v1;
    WRED2(s,q)
    float m = s*(1.f/64.f);
    float r = rsqrtf(fmaxf(q*(1.f/64.f)-m*m, 0.f)+LN_EPS);
    ys[f*64+lane]    = (v0-m)*r*par[lane]    + par[64+lane];
    ys[f*64+lane+32] = (v1-m)*r*par[32+lane] + par[96+lane];
  }
  __syncthreads();

  // grouped conv (K=3, G=8) with register sliding window + leaky + residual
  {
    const int c = tid & 63, chunk = tid >> 6;
    const int f0 = chunk*33, f1 = min(FR, f0+33);
    const int gb = c & 56;
    float w[24];
    #pragma unroll
    for (int j = 0; j < 24; ++j) w[j] = wc[j*64 + c];
    const float cb = par[128+c];
    float rm1[8], r0[8], rp1[8];
    LDROW(f0-1, rm1)
    LDROW(f0,   r0)
    float* x1dst = g_x1 + (size_t)n*FR*CC;
    for (int f = f0; f < f1; ++f) {
      LDROW(f+1, rp1)
      float acc = cb;
      #pragma unroll
      for (int ci = 0; ci < 8; ++ci)
        acc += w[ci]*rm1[ci] + w[8+ci]*r0[ci] + w[16+ci]*rp1[ci];
      float v = xs[f*64+c] + (acc >= 0.f ? acc : alpha*acc);
      xs[f*64+c] = v;
      x1dst[f*64+c] = v;
      #pragma unroll
      for (int j = 0; j < 8; ++j) { rm1[j] = r0[j]; r0[j] = rp1[j]; }
    }
  }
  __syncthreads();

  // LN2 + reduce to CPP via warp shuffles -> hps (aliases ys)
  float* hps = ys;
  for (int f = wid; f < FR; f += 16) {
    float v0 = xs[f*64+lane], v1 = xs[f*64+lane+32];
    float s = v0+v1, q = v0*v0+v1*v1;
    WRED2(s,q)
    float m = s*(1.f/64.f);
    float r = rsqrtf(fmaxf(q*(1.f/64.f)-m*m, 0.f)+LN_EPS);
    float y0 = (v0-m)*r*par[192+lane] + par[256+lane];
    float y1 = (v1-m)*r*par[224+lane] + par[288+lane];
    #pragma unroll
    for (int p = 0; p < 16; ++p) {
      float pa = y0*rw[p*64+lane] + y1*rw[p*64+lane+32];
      #pragma unroll
      for (int o = 16; o; o >>= 1) pa += __shfl_xor_sync(0xffffffffu, pa, o);
      if (lane == 0) {
        float v = pa + par[320+p];
        hps[p*FR+f] = v * (1.f/(1.f+__expf(-v)));
      }
    }
  }
  __syncthreads();
  for (int i = tid; i < CPP*FR; i += 512) {
    int p = i / FR;
    g_hp[(size_t)p*NF + (size_t)n*FR + (i - p*FR)] = hps[i];
  }
}

// ---------------------------------------------------------------------------
// K2: per-channel GEMM  hq[n,g,p] = sum_f hp[p,n,f] * fW[p,g,f] + fB[p,g]
//     64x64 tile, BK=16, 4x4 microtile, fp32
// ---------------------------------------------------------------------------
__global__ __launch_bounds__(256) void k_fgemm(const float* __restrict__ fW,
                                               const float* __restrict__ fB)
{
  __shared__ float As[16*68];
  __shared__ float Bs[16*68];
  const int p  = blockIdx.z;
  const int n0 = blockIdx.x * 64, g0 = blockIdx.y * 64;
  const float* A  = g_hp + (size_t)p*NF;       // [NN][FR]
  const float* Bw = fW   + (size_t)p*FR*FR;    // [FR(g)][FR(f)]
  const int tid = threadIdx.x;
  const int ty = tid >> 4, tx = tid & 15;
  float acc[4][4];
  #pragma unroll
  for (int i = 0; i < 4; ++i)
    #pragma unroll
    for (int j = 0; j < 4; ++j) acc[i][j] = 0.f;

  for (int f0 = 0; f0 < FR; f0 += 16) {
    #pragma unroll
    for (int j = 0; j < 4; ++j) {
      int li = tid + j*256;
      int m = li >> 4, k = li & 15;
      int ff = f0 + k;
      int nn = n0 + m;
      As[k*68+m] = (nn < NN && ff < FR) ? A[(size_t)nn*FR + ff] : 0.f;
      int gg = g0 + m;
      Bs[k*68+m] = (gg < FR && ff < FR) ? Bw[gg*FR + ff] : 0.f;
    }
    __syncthreads();
    #pragma unroll
    for (int k = 0; k < 16; ++k) {
      float4 a4 = ((const float4*)As)[k*17 + ty];
      float4 b4 = ((const float4*)Bs)[k*17 + tx];
      float ra[4] = {a4.x, a4.y, a4.z, a4.w};
      float rb[4] = {b4.x, b4.y, b4.z, b4.w};
      #pragma unroll
      for (int i = 0; i < 4; ++i)
        #pragma unroll
        for (int j = 0; j < 4; ++j)
          acc[i][j] += ra[i]*rb[j];
    }
    __syncthreads();
  }
  #pragma unroll
  for (int i = 0; i < 4; ++i) {
    int nn = n0 + ty*4 + i;
    if (nn < NN) {
      #pragma unroll
      for (int j = 0; j < 4; ++j) {
        int gg = g0 + tx*4 + j;
        if (gg < FR)
          g_hq[((size_t)nn*FR + gg)*CPP + p] = acc[i][j] + fB[p*FR + gg];
      }
    }
  }
}

// ---------------------------------------------------------------------------
// K3: expand + silu + residual, then freq_conv #2, scatter to output layout
// ---------------------------------------------------------------------------
__global__ __launch_bounds__(512) void k_freq2(
    float* __restrict__ out,
    const float* __restrict__ ew_, const float* __restrict__ eb_,
    const float* __restrict__ g2, const float* __restrict__ b2,
    const float* __restrict__ w2, const float* __restrict__ cb2,
    const float* __restrict__ a2)
{
  extern __shared__ float sm[];
  float* xs  = sm;                 // [FR*64]
  float* ys  = xs + FR*CC;         // [FR*64]
  float* hqs = ys + FR*CC;         // [FR*16]
  float* wc  = hqs + FR*CPP;       // [24*64]
  float* ewt = wc + 24*CC;         // [p][c]
  float* par = ewt + CPP*CC;       // eb|g2|b2|cb2 (64 each)

  const int tid = threadIdx.x;
  const int n = blockIdx.x;
  const int b = n / TT, t = n % TT;

  if (tid < CC) {
    par[tid] = eb_[tid]; par[64+tid] = g2[tid];
    par[128+tid] = b2[tid]; par[192+tid] = cb2[tid];
  }
  for (int i = tid; i < 24*CC; i += 512) {
    int c = i & 63, kk = i >> 6, k = kk >> 3, ci = kk & 7;
    wc[i] = w2[c*24 + ci*3 + k];
  }
  for (int i = tid; i < CPP*CC; i += 512) {
    int p = i >> 6, c = i & 63;
    ewt[i] = ew_[c*CPP + p];
  }
  const float alpha = __ldg(a2);
  float4* xs4 = (float4*)xs;
  const float4* x1src = (const float4*)(g_x1 + (size_t)n*FR*CC);
  for (int i = tid; i < FR*16; i += 512) xs4[i] = x1src[i];
  float4* hq4 = (float4*)hqs;
  const float4* hqsrc = (const float4*)(g_hq + (size_t)n*FR*CPP);
  for (int i = tid; i < FR*4; i += 512) hq4[i] = hqsrc[i];
  __syncthreads();

  const int wid = tid >> 5, lane = tid & 31;
  // expand + silu + residual (column sweep, exp_w in regs)
  {
    const int c = tid & 63, chunk = tid >> 6;
    const int f0 = chunk*33, f1 = min(FR, f0+33);
    float ew[16];
    #pragma unroll
    for (int p = 0; p < 16; ++p) ew[p] = ewt[p*64 + c];
    const float ebv = par[c];
    for (int f = f0; f < f1; ++f) {
      float4 h0 = ((const float4*)(hqs + f*16))[0];
      float4 h1 = ((const float4*)(hqs + f*16))[1];
      float4 h2 = ((const float4*)(hqs + f*16))[2];
      float4 h3 = ((const float4*)(hqs + f*16))[3];
      float acc = ebv;
      acc += ew[0]*h0.x + ew[1]*h0.y + ew[2]*h0.z + ew[3]*h0.w;
      acc += ew[4]*h1.x + ew[5]*h1.y + ew[6]*h1.z + ew[7]*h1.w;
      acc += ew[8]*h2.x + ew[9]*h2.y + ew[10]*h2.z + ew[11]*h2.w;
      acc += ew[12]*h3.x + ew[13]*h3.y + ew[14]*h3.z + ew[15]*h3.w;
      float sv = acc * (1.f/(1.f+__expf(-acc)));
      xs[f*64+c] += sv;
    }
  }
  __syncthreads();

  // LN -> ys
  for (int f = wid; f < FR; f += 16) {
    float v0 = xs[f*64+lane], v1 = xs[f*64+lane+32];
    float s = v0+v1, q = v0*v0+v1*v1;
    WRED2(s,q)
    float m = s*(1.f/64.f);
    float r = rsqrtf(fmaxf(q*(1.f/64.f)-m*m, 0.f)+LN_EPS);
    ys[f*64+lane]    = (v0-m)*r*par[64+lane] + par[128+lane];
    ys[f*64+lane+32] = (v1-m)*r*par[96+lane] + par[160+lane];
  }
  __syncthreads();

  // conv #2 + leaky + residual, store to [B,FR,T,C]
  {
    const int c = tid & 63, chunk = tid >> 6;
    const int f0 = chunk*33, f1 = min(FR, f0+33);
    const int gb = c & 56;
    float w[24];
    #pragma unroll
    for (int j = 0; j < 24; ++j) w[j] = wc[j*64 + c];
    const float cb = par[192+c];
    float rm1[8], r0[8], rp1[8];
    LDROW(f0-1, rm1)
    LDROW(f0,   r0)
    float* obase = out + ((size_t)b*FR*TT + t)*CC;
    for (int f = f0; f < f1; ++f) {
      LDROW(f+1, rp1)
      float acc = cb;
      #pragma unroll
      for (int ci = 0; ci < 8; ++ci)
        acc += w[ci]*rm1[ci] + w[8+ci]*r0[ci] + w[16+ci]*rp1[ci];
      float v = xs[f*64+c] + (acc >= 0.f ? acc : alpha*acc);
      obase[(size_t)f*TT*CC + c] = v;
      #pragma unroll
      for (int j = 0; j < 8; ++j) { rm1[j] = r0[j]; r0[j] = rp1[j]; }
    }
  }
}

// ---------------------------------------------------------------------------
extern "C" void kernel_launch(void* const* d_in, const int* in_sizes, int n_in,
                              void* d_out, int out_size)
{
  const float* h     = (const float*)d_in[0];
  const float* fc1g  = (const float*)d_in[1];
  const float* fc1b  = (const float*)d_in[2];
  const float* fc1w  = (const float*)d_in[3];
  const float* fc1cb = (const float*)d_in[4];
  const float* fc1a  = (const float*)d_in[5];
  const float* fblg  = (const float*)d_in[6];
  const float* fblb  = (const float*)d_in[7];
  const float* redw  = (const float*)d_in[8];
  const float* redb  = (const float*)d_in[9];
  const float* fW    = (const float*)d_in[10];
  const float* fB    = (const float*)d_in[11];
  const float* expw  = (const float*)d_in[12];
  const float* expb  = (const float*)d_in[13];
  const float* fc2g  = (const float*)d_in[14];
  const float* fc2b  = (const float*)d_in[15];
  const float* fc2w  = (const float*)d_in[16];
  const float* fc2cb = (const float*)d_in[17];
  const float* fc2a  = (const float*)d_in[18];
  float* out = (float*)d_out;

  const int SM1 = (2*FR*CC + 24*CC + CPP*CC + 5*64 + 16) * 4;
  const int SM3 = (2*FR*CC + FR*CPP + 24*CC + CPP*CC + 4*64) * 4;
  cudaFuncSetAttribute(k_freq1, cudaFuncAttributeMaxDynamicSharedMemorySize, SM1);
  cudaFuncSetAttribute(k_freq2, cudaFuncAttributeMaxDynamicSharedMemorySize, SM3);

  k_freq1<<<NN, 512, SM1>>>(h, fc1g, fc1b, fc1w, fc1cb, fc1a,
                            fblg, fblb, redw, redb);
  dim3 gg((NN+63)/64, (FR+63)/64, CPP);
  k_fgemm<<<gg, 256>>>(fW, fB);
  k_freq2<<<NN, 512, SM3>>>(out, expw, expb, fc2g, fc2b, fc2w, fc2cb, fc2a);
}

// round 2
// speedup vs baseline: 2.3301x; 2.3301x over previous
#include <cuda_runtime.h>
#include <math.h>

#define BB 8
#define FR 257
#define TT 300
#define CC 64
#define CPP 16
#define NN (BB*TT)              /* 2400 */
#define NF ((size_t)NN*FR)      /* 616800 */
#define LN_EPS 1e-5f
#define CH 65                   /* F-chunk size; 4 chunks: 65,65,65,62 */

// Scratch (device globals: allocation-free per harness rules)
__device__ float g_x1[(size_t)NN*FR*CC];   // stage-1 output  [n][f][c]
__device__ float g_hp[(size_t)CPP*NN*FR];  // reduced hidden  [p][n][f]
__device__ float g_hq[(size_t)NN*FR*CPP];  // fW GEMM output  [n][f][p]

typedef unsigned long long ull;

__device__ __forceinline__ ull pk2(float lo, float hi) {
  ull d; asm("mov.b64 %0, {%1,%2};" : "=l"(d) : "f"(lo), "f"(hi)); return d;
}
__device__ __forceinline__ void ffma2(ull& d, ull a, ull b) {
  asm("fma.rn.f32x2 %0, %1, %2, %0;" : "+l"(d) : "l"(a), "l"(b));
}
__device__ __forceinline__ void upk2(float& lo, float& hi, ull v) {
  asm("mov.b64 {%0,%1}, %2;" : "=f"(lo), "=f"(hi) : "l"(v));
}

// Load one 8-wide group row of ys (global index F, zero outside [0,FR)).
#define LDROWG(F, R) { \
  if ((unsigned)(F) < (unsigned)FR) { int _lr = (F) - e0; \
    float4 _a = *(const float4*)(ys + _lr*64 + gb); \
    float4 _b = *(const float4*)(ys + _lr*64 + gb + 4); \
    (R)[0]=_a.x;(R)[1]=_a.y;(R)[2]=_a.z;(R)[3]=_a.w; \
    (R)[4]=_b.x;(R)[5]=_b.y;(R)[6]=_b.z;(R)[7]=_b.w; \
  } else { \
    _Pragma("unroll") for (int _j=0;_j<8;_j++) (R)[_j]=0.f; \
  } }

#define WRED2(S,Q) { _Pragma("unroll") for (int _o=16;_o;_o>>=1){ \
  (S) += __shfl_xor_sync(0xffffffffu,(S),_o); \
  (Q) += __shfl_xor_sync(0xffffffffu,(Q),_o);} }

// ---------------------------------------------------------------------------
// K1: freq_conv #1 + LN2 + reduce-to-CPP   (CTA = (n, F-chunk))
// smem floats: XS 4288 | YT 4352 | WC 1536 | RW 1024 | PAR 336  = 11536
// ---------------------------------------------------------------------------
__global__ __launch_bounds__(256) void k_freq1(
    const float* __restrict__ h,
    const float* __restrict__ g1, const float* __restrict__ b1,
    const float* __restrict__ w1, const float* __restrict__ cb1,
    const float* __restrict__ a1,
    const float* __restrict__ fg, const float* __restrict__ fbv,
    const float* __restrict__ rw_, const float* __restrict__ rb_)
{
  extern __shared__ float sm[];
  float* xs  = sm;            // [67*64] input rows (incl halo), then conv out
  float* ys  = xs + 67*64;    // LN1 out [ne*64]; later yt transposed [64*68]
  float* wc  = ys + 64*68;    // [(k*8+ci)][c]
  float* rw  = wc + 24*CC;    // [p][c]
  float* par = rw + CPP*CC;   // g1|b1|cb|fg|fb (64 each) + rb(16)

  const int tid = threadIdx.x;
  const int n = blockIdx.x;
  const int b = n / TT, t = n % TT;
  const int f0 = blockIdx.y * CH;
  const int f1 = min(FR, f0 + CH);
  const int nf = f1 - f0;
  const int e0 = (f0 > 0) ? f0 - 1 : 0;
  const int e1 = (f1 < FR) ? f1 + 1 : FR;
  const int ne = e1 - e0;

  if (tid < CC) {
    par[tid]     = g1[tid];  par[64+tid]  = b1[tid];  par[128+tid] = cb1[tid];
    par[192+tid] = fg[tid];  par[256+tid] = fbv[tid];
  }
  if (tid >= 64 && tid < 64+CPP) par[320 + (tid-64)] = rb_[tid-64];
  for (int i = tid; i < 24*CC; i += 256) {
    int c = i & 63, kk = i >> 6, k = kk >> 3, ci = kk & 7;
    wc[i] = w1[c*24 + ci*3 + k];
  }
  for (int i = tid; i < CPP*CC; i += 256) rw[i] = rw_[i];

  const float alpha = __ldg(a1);
  const float* hbase = h + ((size_t)b*FR*TT + t)*CC;
  float4* xs4 = (float4*)xs;
  for (int i = tid; i < ne*16; i += 256) {
    int r = i >> 4, q = i & 15;
    xs4[i] = ((const float4*)(hbase + (size_t)(e0+r)*TT*CC))[q];
  }
  __syncthreads();

  const int wid = tid >> 5, lane = tid & 31;
  // LN1 over all ne rows -> ys (stride 64)
  for (int r = wid; r < ne; r += 8) {
    float v0 = xs[r*64+lane], v1 = xs[r*64+lane+32];
    float s = v0+v1, q = v0*v0+v1*v1;
    WRED2(s,q)
    float m = s*(1.f/64.f);
    float rr = rsqrtf(fmaxf(q*(1.f/64.f)-m*m, 0.f)+LN_EPS);
    ys[r*64+lane]    = (v0-m)*rr*par[lane]    + par[64+lane];
    ys[r*64+lane+32] = (v1-m)*rr*par[32+lane] + par[96+lane];
  }
  __syncthreads();

  // grouped conv (K=3, G=8) sliding window + leaky + residual
  {
    const int c = tid & 63, rowg = tid >> 6;
    const int sub = (nf + 3) >> 2;
    const int fs = f0 + rowg*sub, fe = min(f1, fs + sub);
    const int gb = c & 56;
    float w[24];
    #pragma unroll
    for (int j = 0; j < 24; ++j) w[j] = wc[j*64 + c];
    const float cb = par[128+c];
    float rm1[8], r0[8], rp1[8];
    LDROWG(fs-1, rm1)
    LDROWG(fs,   r0)
    float* x1dst = g_x1 + (size_t)n*FR*CC;
    for (int f = fs; f < fe; ++f) {
      LDROWG(f+1, rp1)
      float acc = cb;
      #pragma unroll
      for (int ci = 0; ci < 8; ++ci)
        acc += w[ci]*rm1[ci] + w[8+ci]*r0[ci] + w[16+ci]*rp1[ci];
      int le = f - e0;
      float v = xs[le*64+c] + (acc >= 0.f ? acc : alpha*acc);
      xs[le*64+c] = v;
      x1dst[(size_t)f*64+c] = v;
      #pragma unroll
      for (int j = 0; j < 8; ++j) { rm1[j] = r0[j]; r0[j] = rp1[j]; }
    }
  }
  __syncthreads();

  // LN2 -> transposed yt[c][flo] (stride 68), aliases ys
  float* yt = ys;
  for (int fo = wid; fo < nf; fo += 8) {
    int le = fo + (e0 < f0);
    float v0 = xs[le*64+lane], v1 = xs[le*64+lane+32];
    float s = v0+v1, q = v0*v0+v1*v1;
    WRED2(s,q)
    float m = s*(1.f/64.f);
    float rr = rsqrtf(fmaxf(q*(1.f/64.f)-m*m, 0.f)+LN_EPS);
    yt[lane*68+fo]      = (v0-m)*rr*par[192+lane] + par[256+lane];
    yt[(lane+32)*68+fo] = (v1-m)*rr*par[224+lane] + par[288+lane];
  }
  __syncthreads();

  // reduce: warp w handles p = {w, w+8}; lanes cover fl stride-32
  {
    const int fl1 = lane + 32;
    const int fl2c = min(lane + 64, 67);
    for (int pp = 0; pp < 2; ++pp) {
      const int p = wid + pp*8;
      const float* rwp = rw + p*64;
      float a0 = 0.f, a1 = 0.f, a2 = 0.f;
      #pragma unroll 8
      for (int c = 0; c < 64; ++c) {
        float rc = rwp[c];
        const float* yr = yt + c*68;
        a0 += rc * yr[lane];
        a1 += rc * yr[fl1];
        a2 += rc * yr[fl2c];
      }
      const float rbvp = par[320+p];
      float* dst = g_hp + (size_t)p*NF + (size_t)n*FR + f0;
      if (lane < nf)     { float v=a0+rbvp; dst[lane]    = v/(1.f+__expf(-v)); }
      if (fl1 < nf)      { float v=a1+rbvp; dst[fl1]     = v/(1.f+__expf(-v)); }
      if (lane+64 < nf)  { float v=a2+rbvp; dst[lane+64] = v/(1.f+__expf(-v)); }
    }
  }
}

// ---------------------------------------------------------------------------
// K2: per-channel GEMM  hq[n,g,p] = sum_f hp[p,n,f] * fW[p,g,f] + fB[p,g]
//     128x64 tile, BK=16, 8x4 microtile, packed f32x2 FMA
// ---------------------------------------------------------------------------
__global__ __launch_bounds__(256) void k_fgemm(const float* __restrict__ fW,
                                               const float* __restrict__ fB)
{
  __shared__ float As[16*132];
  __shared__ float Bs[16*68];
  __shared__ float fBs[64];
  const int p  = blockIdx.z;
  const int n0 = blockIdx.x * 128, g0 = blockIdx.y * 64;
  const float* A  = g_hp + (size_t)p*NF;       // [NN][FR]
  const float* Bw = fW   + (size_t)p*FR*FR;    // [FR(g)][FR(f)]
  const int tid = threadIdx.x;
  const int ty = tid >> 4, tx = tid & 15;
  if (tid < 64) fBs[tid] = (g0+tid < FR) ? fB[p*FR + g0 + tid] : 0.f;

  ull acc[8][2];
  #pragma unroll
  for (int i = 0; i < 8; ++i) { acc[i][0] = 0ull; acc[i][1] = 0ull; }

  for (int ft = 0; ft < FR; ft += 16) {
    #pragma unroll
    for (int j = 0; j < 8; ++j) {
      int li = tid + j*256;
      int k = li & 15, m = li >> 4;
      int ff = ft + k, nn = n0 + m;
      As[k*132+m] = (nn < NN && ff < FR) ? A[(size_t)nn*FR + ff] : 0.f;
    }
    #pragma unroll
    for (int j = 0; j < 4; ++j) {
      int li = tid + j*256;
      int k = li & 15, m = li >> 4;
      int ff = ft + k, gg = g0 + m;
      Bs[k*68+m] = (gg < FR && ff < FR) ? Bw[gg*FR + ff] : 0.f;
    }
    __syncthreads();
    #pragma unroll
    for (int k = 0; k < 16; ++k) {
      float4 a0 = *(const float4*)&As[k*132 + ty*8];
      float4 a1 = *(const float4*)&As[k*132 + ty*8 + 4];
      float4 bv = *(const float4*)&Bs[k*68 + tx*4];
      ull b01 = pk2(bv.x, bv.y), b23 = pk2(bv.z, bv.w);
      float av[8] = {a0.x,a0.y,a0.z,a0.w,a1.x,a1.y,a1.z,a1.w};
      #pragma unroll
      for (int i = 0; i < 8; ++i) {
        ull aa = pk2(av[i], av[i]);
        ffma2(acc[i][0], aa, b01);
        ffma2(acc[i][1], aa, b23);
      }
    }
    __syncthreads();
  }
  #pragma unroll
  for (int i = 0; i < 8; ++i) {
    int nn = n0 + ty*8 + i;
    if (nn >= NN) continue;
    float o0,o1,o2,o3;
    upk2(o0,o1,acc[i][0]);
    upk2(o2,o3,acc[i][1]);
    float ov[4] = {o0,o1,o2,o3};
    #pragma unroll
    for (int j = 0; j < 4; ++j) {
      int gg = g0 + tx*4 + j;
      if (gg < FR)
        g_hq[((size_t)nn*FR + gg)*CPP + p] = ov[j] + fBs[tx*4+j];
    }
  }
}

// ---------------------------------------------------------------------------
// K3: expand + silu + residual, LN, freq_conv #2, scatter to output
// smem floats: XS 4288 | YS 4288 | HQ 1072 | WC 1536 | EW 1024 | PAR 256
// ---------------------------------------------------------------------------
__global__ __launch_bounds__(256) void k_freq2(
    float* __restrict__ out,
    const float* __restrict__ ew_, const float* __restrict__ eb_,
    const float* __restrict__ g2, const float* __restrict__ b2,
    const float* __restrict__ w2, const float* __restrict__ cb2,
    const float* __restrict__ a2)
{
  extern __shared__ float sm[];
  float* xs  = sm;            // [67*64]
  float* ys  = xs + 67*64;    // [67*64]
  float* hqs = ys + 67*64;    // [67*16]
  float* wc  = hqs + 67*CPP;  // [24*64]
  float* ewt = wc + 24*CC;    // [p][c]
  float* par = ewt + CPP*CC;  // eb|g2|b2|cb2 (64 each)

  const int tid = threadIdx.x;
  const int n = blockIdx.x;
  const int b = n / TT, t = n % TT;
  const int f0 = blockIdx.y * CH;
  const int f1 = min(FR, f0 + CH);
  const int nf = f1 - f0;
  const int e0 = (f0 > 0) ? f0 - 1 : 0;
  const int e1 = (f1 < FR) ? f1 + 1 : FR;
  const int ne = e1 - e0;

  if (tid < CC) {
    par[tid] = eb_[tid]; par[64+tid] = g2[tid];
    par[128+tid] = b2[tid]; par[192+tid] = cb2[tid];
  }
  for (int i = tid; i < 24*CC; i += 256) {
    int c = i & 63, kk = i >> 6, k = kk >> 3, ci = kk & 7;
    wc[i] = w2[c*24 + ci*3 + k];
  }
  for (int i = tid; i < CPP*CC; i += 256) {
    int p = i >> 6, c = i & 63;
    ewt[i] = ew_[c*CPP + p];
  }
  const float alpha = __ldg(a2);
  float4* xs4 = (float4*)xs;
  const float4* x1src = (const float4*)(g_x1 + ((size_t)n*FR + e0)*CC);
  for (int i = tid; i < ne*16; i += 256) xs4[i] = x1src[i];
  float4* hq4 = (float4*)hqs;
  const float4* hqsrc = (const float4*)(g_hq + ((size_t)n*FR + e0)*CPP);
  for (int i = tid; i < ne*4; i += 256) hq4[i] = hqsrc[i];
  __syncthreads();

  const int wid = tid >> 5, lane = tid & 31;
  // expand + silu + residual for all ne rows (halo needed by LN+conv)
  {
    const int c = tid & 63, rowg = tid >> 6;
    float ew[16];
    #pragma unroll
    for (int p = 0; p < 16; ++p) ew[p] = ewt[p*64 + c];
    const float ebv = par[c];
    for (int r = rowg; r < ne; r += 4) {
      float4 h0 = ((const float4*)(hqs + r*16))[0];
      float4 h1 = ((const float4*)(hqs + r*16))[1];
      float4 h2 = ((const float4*)(hqs + r*16))[2];
      float4 h3 = ((const float4*)(hqs + r*16))[3];
      float acc = ebv;
      acc += ew[0]*h0.x + ew[1]*h0.y + ew[2]*h0.z + ew[3]*h0.w;
      acc += ew[4]*h1.x + ew[5]*h1.y + ew[6]*h1.z + ew[7]*h1.w;
      acc += ew[8]*h2.x + ew[9]*h2.y + ew[10]*h2.z + ew[11]*h2.w;
      acc += ew[12]*h3.x + ew[13]*h3.y + ew[14]*h3.z + ew[15]*h3.w;
      float sv = acc * (1.f/(1.f+__expf(-acc)));
      xs[r*64+c] += sv;
    }
  }
  __syncthreads();

  // LN over all ne rows -> ys
  for (int r = wid; r < ne; r += 8) {
    float v0 = xs[r*64+lane], v1 = xs[r*64+lane+32];
    float s = v0+v1, q = v0*v0+v1*v1;
    WRED2(s,q)
    float m = s*(1.f/64.f);
    float rr = rsqrtf(fmaxf(q*(1.f/64.f)-m*m, 0.f)+LN_EPS);
    ys[r*64+lane]    = (v0-m)*rr*par[64+lane] + par[128+lane];
    ys[r*64+lane+32] = (v1-m)*rr*par[96+lane] + par[160+lane];
  }
  __syncthreads();

  // conv #2 + leaky + residual, store to [B,FR,T,C]
  {
    const int c = tid & 63, rowg = tid >> 6;
    const int sub = (nf + 3) >> 2;
    const int fs = f0 + rowg*sub, fe = min(f1, fs + sub);
    const int gb = c & 56;
    float w[24];
    #pragma unroll
    for (int j = 0; j < 24; ++j) w[j] = wc[j*64 + c];
    const float cb = par[192+c];
    float rm1[8], r0[8], rp1[8];
    LDROWG(fs-1, rm1)
    LDROWG(fs,   r0)
    float* obase = out + ((size_t)b*FR*TT + t)*CC;
    for (int f = fs; f < fe; ++f) {
      LDROWG(f+1, rp1)
      float acc = cb;
      #pragma unroll
      for (int ci = 0; ci < 8; ++ci)
        acc += w[ci]*rm1[ci] + w[8+ci]*r0[ci] + w[16+ci]*rp1[ci];
      float v = xs[(f-e0)*64+c] + (acc >= 0.f ? acc : alpha*acc);
      obase[(size_t)f*TT*CC + c] = v;
      #pragma unroll
      for (int j = 0; j < 8; ++j) { rm1[j] = r0[j]; r0[j] = rp1[j]; }
    }
  }
}

// ---------------------------------------------------------------------------
extern "C" void kernel_launch(void* const* d_in, const int* in_sizes, int n_in,
                              void* d_out, int out_size)
{
  const float* h     = (const float*)d_in[0];
  const float* fc1g  = (const float*)d_in[1];
  const float* fc1b  = (const float*)d_in[2];
  const float* fc1w  = (const float*)d_in[3];
  const float* fc1cb = (const float*)d_in[4];
  const float* fc1a  = (const float*)d_in[5];
  const float* fblg  = (const float*)d_in[6];
  const float* fblb  = (const float*)d_in[7];
  const float* redw  = (const float*)d_in[8];
  const float* redb  = (const float*)d_in[9];
  const float* fW    = (const float*)d_in[10];
  const float* fB    = (const float*)d_in[11];
  const float* expw  = (const float*)d_in[12];
  const float* expb  = (const float*)d_in[13];
  const float* fc2g  = (const float*)d_in[14];
  const float* fc2b  = (const float*)d_in[15];
  const float* fc2w  = (const float*)d_in[16];
  const float* fc2cb = (const float*)d_in[17];
  const float* fc2a  = (const float*)d_in[18];
  float* out = (float*)d_out;

  const int SM1 = (67*64 + 64*68 + 24*CC + CPP*CC + 336) * 4;
  const int SM3 = (67*64 + 67*64 + 67*CPP + 24*CC + CPP*CC + 256) * 4;
  cudaFuncSetAttribute(k_freq1, cudaFuncAttributeMaxDynamicSharedMemorySize, SM1);
  cudaFuncSetAttribute(k_freq2, cudaFuncAttributeMaxDynamicSharedMemorySize, SM3);

  dim3 g1(NN, 4);
  k_freq1<<<g1, 256, SM1>>>(h, fc1g, fc1b, fc1w, fc1cb, fc1a,
                            fblg, fblb, redw, redb);
  dim3 gg((NN+127)/128, (FR+63)/64, CPP);
  k_fgemm<<<gg, 256>>>(fW, fB);
  dim3 g3(NN, 4);
  k_freq2<<<g3, 256, SM3>>>(out, expw, expb, fc2g, fc2b, fc2w, fc2cb, fc2a);
}

// round 5
// speedup vs baseline: 2.7461x; 1.1785x over previous
#include <cuda_runtime.h>
#include <math.h>

#define BB 8
#define FR 257
#define FRP 260                 /* padded row length for g_hp (float4 align) */
#define TT 300
#define CC 64
#define CPP 16
#define NN (BB*TT)              /* 2400 */
#define NFP ((size_t)NN*FRP)
#define LN_EPS 1e-5f
#define CH 65                   /* F-chunk size; 4 chunks */
#define KC 32                   /* K2 k-chunk */

// Scratch (device globals: allocation-free per harness rules)
__device__ float g_x1[(size_t)NN*FR*CC];    // stage-1 output  [n][f][c]
__device__ float g_hp[(size_t)CPP*NN*FRP];  // reduced hidden  [p][n][fpad]
__device__ float g_hq[(size_t)NN*FR*CPP];   // fW GEMM output  [n][f][p]

typedef unsigned long long ull;

__device__ __forceinline__ ull pk2(float lo, float hi) {
  ull d; asm("mov.b64 %0, {%1,%2};" : "=l"(d) : "f"(lo), "f"(hi)); return d;
}
__device__ __forceinline__ void ffma2(ull& d, ull a, ull b) {
  asm("fma.rn.f32x2 %0, %1, %2, %0;" : "+l"(d) : "l"(a), "l"(b));
}
__device__ __forceinline__ void upk2(float& lo, float& hi, ull v) {
  asm("mov.b64 {%0,%1}, %2;" : "=f"(lo), "=f"(hi) : "l"(v));
}
__device__ __forceinline__ float to_tf32(float x) {
  float y;
  asm("cvt.rna.tf32.f32 %0, %1;" : "=f"(y) : "f"(x));
  return y;
}

// Load one 8-wide group row of ys as 4 ulls (global index F, zero outside).
#define LDROWU(F, R) { \
  if ((unsigned)(F) < (unsigned)FR) { int _lr = (F) - e0; \
    longlong2 _a = *(const longlong2*)(ys + _lr*64 + gb); \
    longlong2 _b = *(const longlong2*)(ys + _lr*64 + gb + 4); \
    (R)[0]=(ull)_a.x;(R)[1]=(ull)_a.y;(R)[2]=(ull)_b.x;(R)[3]=(ull)_b.y; \
  } else { \
    _Pragma("unroll") for (int _j=0;_j<4;_j++) (R)[_j]=0ull; \
  } }

#define WRED2(S,Q) { _Pragma("unroll") for (int _o=16;_o;_o>>=1){ \
  (S) += __shfl_xor_sync(0xffffffffu,(S),_o); \
  (Q) += __shfl_xor_sync(0xffffffffu,(Q),_o);} }

// ---------------------------------------------------------------------------
// K1: freq_conv #1 + LN2 + reduce-to-CPP   (CTA = (n, F-chunk))
// ---------------------------------------------------------------------------
__global__ __launch_bounds__(256, 4) void k_freq1(
    const float* __restrict__ h,
    const float* __restrict__ g1, const float* __restrict__ b1,
    const float* __restrict__ w1, const float* __restrict__ cb1,
    const float* __restrict__ a1,
    const float* __restrict__ fg, const float* __restrict__ fbv,
    const float* __restrict__ rw_, const float* __restrict__ rb_)
{
  extern __shared__ float sm[];
  float* xs  = sm;            // [67*64]
  float* ys  = xs + 67*64;    // LN1 out stride 64; later yt stride 65
  float* wc  = ys + 67*64;    // [(k*8+ci)][c]
  float* rwT = wc + 24*CC;    // [c][p]  64x16
  float* par = rwT + CC*CPP;  // g1|b1|cb|fg|fb (64 each) + rb(16)

  const int tid = threadIdx.x;
  const int n = blockIdx.x;
  const int b = n / TT, t = n % TT;
  const int f0 = blockIdx.y * CH;
  const int f1 = min(FR, f0 + CH);
  const int nf = f1 - f0;
  const int e0 = (f0 > 0) ? f0 - 1 : 0;
  const int e1 = (f1 < FR) ? f1 + 1 : FR;
  const int ne = e1 - e0;

  if (tid < CC) {
    par[tid]     = g1[tid];  par[64+tid]  = b1[tid];  par[128+tid] = cb1[tid];
    par[192+tid] = fg[tid];  par[256+tid] = fbv[tid];
  }
  if (tid >= 64 && tid < 64+CPP) par[320 + (tid-64)] = rb_[tid-64];
  for (int i = tid; i < 24*CC; i += 256) {
    int c = i & 63, kk = i >> 6, k = kk >> 3, ci = kk & 7;
    wc[i] = w1[c*24 + ci*3 + k];
  }
  for (int i = tid; i < CC*CPP; i += 256) {
    int c = i >> 4, p = i & 15;
    rwT[i] = rw_[p*64 + c];
  }

  const float alpha = __ldg(a1);
  const float* hbase = h + ((size_t)b*FR*TT + t)*CC;
  float4* xs4 = (float4*)xs;
  for (int i = tid; i < ne*16; i += 256) {
    int r = i >> 4, q = i & 15;
    xs4[i] = ((const float4*)(hbase + (size_t)(e0+r)*TT*CC))[q];
  }
  __syncthreads();

  const int wid = tid >> 5, lane = tid & 31;
  // LN1 over all ne rows -> ys (stride 64)
  for (int r = wid; r < ne; r += 8) {
    float v0 = xs[r*64+lane], v1 = xs[r*64+lane+32];
    float s = v0+v1, q = v0*v0+v1*v1;
    WRED2(s,q)
    float m = s*(1.f/64.f);
    float rr = rsqrtf(fmaxf(q*(1.f/64.f)-m*m, 0.f)+LN_EPS);
    ys[r*64+lane]    = (v0-m)*rr*par[lane]    + par[64+lane];
    ys[r*64+lane+32] = (v1-m)*rr*par[32+lane] + par[96+lane];
  }
  __syncthreads();

  // grouped conv (K=3, G=8) sliding window (f32x2) + leaky + residual
  {
    const int c = tid & 63, rowg = tid >> 6;
    const int sub = (nf + 3) >> 2;
    const int fs = f0 + rowg*sub, fe = min(f1, fs + sub);
    const int gb = c & 56;
    ull w2[12];
    #pragma unroll
    for (int j = 0; j < 12; ++j)
      w2[j] = pk2(wc[(2*j)*64 + c], wc[(2*j+1)*64 + c]);
    const float cb = par[128+c];
    ull rm2[4], r02[4], rp2[4];
    LDROWU(fs-1, rm2)
    LDROWU(fs,   r02)
    float* x1dst = g_x1 + (size_t)n*FR*CC;
    for (int f = fs; f < fe; ++f) {
      LDROWU(f+1, rp2)
      ull acc2 = pk2(cb, 0.f);
      #pragma unroll
      for (int q = 0; q < 4; ++q) {
        ffma2(acc2, rm2[q], w2[q]);
        ffma2(acc2, r02[q], w2[4+q]);
        ffma2(acc2, rp2[q], w2[8+q]);
      }
      float alo, ahi; upk2(alo, ahi, acc2);
      float acc = alo + ahi;
      int le = f - e0;
      float v = xs[le*64+c] + (acc >= 0.f ? acc : alpha*acc);
      xs[le*64+c] = v;
      x1dst[(size_t)f*64+c] = v;
      #pragma unroll
      for (int j = 0; j < 4; ++j) { rm2[j] = r02[j]; r02[j] = rp2[j]; }
    }
  }
  __syncthreads();

  // LN2 -> transposed yt[c][flo] (stride 65), aliases ys
  float* yt = ys;
  for (int fo = wid; fo < nf; fo += 8) {
    int le = fo + (e0 < f0);
    float v0 = xs[le*64+lane], v1 = xs[le*64+lane+32];
    float s = v0+v1, q = v0*v0+v1*v1;
    WRED2(s,q)
    float m = s*(1.f/64.f);
    float rr = rsqrtf(fmaxf(q*(1.f/64.f)-m*m, 0.f)+LN_EPS);
    yt[lane*65+fo]      = (v0-m)*rr*par[192+lane] + par[256+lane];
    yt[(lane+32)*65+fo] = (v1-m)*rr*par[224+lane] + par[288+lane];
  }
  __syncthreads();

  // reduce: warp = (pgrp of 4 p's, fhalf of 32 f's); rwT broadcast per c
  {
    const int pgrp = wid & 3, fhalf = wid >> 2;
    for (int fb = fhalf*32; fb < nf; fb += 64) {
      const int fl = fb + lane;
      const bool ok = fl < nf;
      const int fi = ok ? fl : 0;
      ull a01 = 0ull, a23 = 0ull;
      #pragma unroll 8
      for (int c = 0; c < 64; ++c) {
        float yv = yt[c*65 + fi];
        ull yy = pk2(yv, yv);
        longlong2 rr = *(const longlong2*)(rwT + c*16 + pgrp*4);
        ffma2(a01, yy, (ull)rr.x);
        ffma2(a23, yy, (ull)rr.y);
      }
      if (ok) {
        float v0,v1,v2,v3; upk2(v0,v1,a01); upk2(v2,v3,a23);
        float vv[4] = {v0,v1,v2,v3};
        #pragma unroll
        for (int j = 0; j < 4; ++j) {
          float v = vv[j] + par[320 + pgrp*4 + j];
          g_hp[(size_t)(pgrp*4+j)*NFP + (size_t)n*FRP + f0 + fl]
              = v/(1.f+__expf(-v));
        }
      }
    }
  }
}

// ---------------------------------------------------------------------------
// K2: per-channel GEMM  hq[n,g,p] = sum_f hp[p,n,f] * fW[p,g,f] + fB[p,g]
//     tf32 mma.sync m16n8k8, 128x64 CTA tile, warps 4x2 of 32x32
// ---------------------------------------------------------------------------
__global__ __launch_bounds__(256) void k_fgemm(const float* __restrict__ fW,
                                               const float* __restrict__ fB)
{
  __shared__ float As[128*36];
  __shared__ float Bs[64*36];
  __shared__ float fBs[64];
  const int p  = blockIdx.z;
  const int n0 = blockIdx.x * 128, g0 = blockIdx.y * 64;
  const float* A  = g_hp + (size_t)p*NFP;      // [NN][FRP]
  const float* Bw = fW   + (size_t)p*FR*FR;    // [FR(g)][FR(f)]
  const int tid = threadIdx.x;
  const int lane = tid & 31, wid = tid >> 5;
  const int wm = (wid & 3) * 32, wn = (wid >> 2) * 32;
  const int grp = lane >> 2, tig = lane & 3;
  if (tid < 64) fBs[tid] = (g0+tid < FR) ? fB[p*FR + g0 + tid] : 0.f;

  float acc[2][4][4];
  #pragma unroll
  for (int i = 0; i < 2; ++i)
    #pragma unroll
    for (int j = 0; j < 4; ++j)
      #pragma unroll
      for (int q = 0; q < 4; ++q) acc[i][j][q] = 0.f;

  for (int ft = 0; ft < FR; ft += KC) {
    // stage A [128 x 32] tf32
    #pragma unroll
    for (int j = 0; j < 4; ++j) {
      int u = tid + j*256;
      int row = u >> 3, kq = u & 7;
      int nn = n0 + row, fb = ft + kq*4;
      float4 v; v.x=v.y=v.z=v.w=0.f;
      if (nn < NN) {
        if (fb + 3 < FR) v = *(const float4*)&A[(size_t)nn*FRP + fb];
        else {
          if (fb   < FR) v.x = A[(size_t)nn*FRP + fb];
          if (fb+1 < FR) v.y = A[(size_t)nn*FRP + fb+1];
          if (fb+2 < FR) v.z = A[(size_t)nn*FRP + fb+2];
          if (fb+3 < FR) v.w = A[(size_t)nn*FRP + fb+3];
        }
      }
      v.x = to_tf32(v.x); v.y = to_tf32(v.y); v.z = to_tf32(v.z); v.w = to_tf32(v.w);
      *(float4*)&As[row*36 + kq*4] = v;
    }
    // stage B [64 x 32] tf32 (scalar: fW rows are odd-length)
    #pragma unroll
    for (int j = 0; j < 8; ++j) {
      int u = tid + j*256;
      int row = u >> 5, k = u & 31;
      int gg = g0 + row, ff = ft + k;
      float v = (gg < FR && ff < FR) ? Bw[(size_t)gg*FR + ff] : 0.f;
      Bs[row*36 + k] = to_tf32(v);
    }
    __syncthreads();
    #pragma unroll
    for (int k8 = 0; k8 < 4; ++k8) {
      const int col = k8*8 + tig;
      unsigned a[2][4];
      #pragma unroll
      for (int mt = 0; mt < 2; ++mt) {
        int r = wm + mt*16 + grp;
        a[mt][0] = __float_as_uint(As[r*36 + col]);
        a[mt][1] = __float_as_uint(As[(r+8)*36 + col]);
        a[mt][2] = __float_as_uint(As[r*36 + col + 4]);
        a[mt][3] = __float_as_uint(As[(r+8)*36 + col + 4]);
      }
      #pragma unroll
      for (int nt = 0; nt < 4; ++nt) {
        int rb = wn + nt*8 + grp;
        unsigned b0 = __float_as_uint(Bs[rb*36 + col]);
        unsigned b1 = __float_as_uint(Bs[rb*36 + col + 4]);
        #pragma unroll
        for (int mt = 0; mt < 2; ++mt) {
          asm volatile(
            "mma.sync.aligned.m16n8k8.row.col.f32.tf32.tf32.f32 "
            "{%0,%1,%2,%3},{%4,%5,%6,%7},{%8,%9},{%0,%1,%2,%3};"
            : "+f"(acc[mt][nt][0]), "+f"(acc[mt][nt][1]),
              "+f"(acc[mt][nt][2]), "+f"(acc[mt][nt][3])
            : "r"(a[mt][0]), "r"(a[mt][1]), "r"(a[mt][2]), "r"(a[mt][3]),
              "r"(b0), "r"(b1));
        }
      }
    }
    __syncthreads();
  }
  // store: c0->(r,g) c1->(r,g+1) c2->(r+8,g) c3->(r+8,g+1)
  #pragma unroll
  for (int mt = 0; mt < 2; ++mt) {
    #pragma unroll
    for (int nt = 0; nt < 4; ++nt) {
      int r = n0 + wm + mt*16 + grp;
      int gl = wn + nt*8 + tig*2;
      int g = g0 + gl;
      #pragma unroll
      for (int q = 0; q < 4; ++q) {
        int rr = r + (q >> 1) * 8;
        int gc = g + (q & 1);
        if (rr < NN && gc < FR)
          g_hq[((size_t)rr*FR + gc)*CPP + p] = acc[mt][nt][q] + fBs[gl + (q&1)];
      }
    }
  }
}

// ---------------------------------------------------------------------------
// K3: expand + silu + residual, LN, freq_conv #2, scatter to output
// ---------------------------------------------------------------------------
__global__ __launch_bounds__(256, 4) void k_freq2(
    float* __restrict__ out,
    const float* __restrict__ ew_, const float* __restrict__ eb_,
    const float* __restrict__ g2, const float* __restrict__ b2,
    const float* __restrict__ w2_, const float* __restrict__ cb2,
    const float* __restrict__ a2)
{
  extern __shared__ float sm[];
  float* xs  = sm;            // [67*64]
  float* ys  = xs + 67*64;    // [67*64]
  float* hqs = ys + 67*64;    // [67*16]
  float* wc  = hqs + 67*CPP;  // [24*64]
  float* ewt = wc + 24*CC;    // [p][c]
  float* par = ewt + CPP*CC;  // eb|g2|b2|cb2 (64 each)

  const int tid = threadIdx.x;
  const int n = blockIdx.x;
  const int b = n / TT, t = n % TT;
  const int f0 = blockIdx.y * CH;
  const int f1 = min(FR, f0 + CH);
  const int nf = f1 - f0;
  const int e0 = (f0 > 0) ? f0 - 1 : 0;
  const int e1 = (f1 < FR) ? f1 + 1 : FR;
  const int ne = e1 - e0;

  if (tid < CC) {
    par[tid] = eb_[tid]; par[64+tid] = g2[tid];
    par[128+tid] = b2[tid]; par[192+tid] = cb2[tid];
  }
  for (int i = tid; i < 24*CC; i += 256) {
    int c = i & 63, kk = i >> 6, k = kk >> 3, ci = kk & 7;
    wc[i] = w2_[c*24 + ci*3 + k];
  }
  for (int i = tid; i < CPP*CC; i += 256) {
    int p = i >> 6, c = i & 63;
    ewt[i] = ew_[c*CPP + p];
  }
  const float alpha = __ldg(a2);
  float4* xs4 = (float4*)xs;
  const float4* x1src = (const float4*)(g_x1 + ((size_t)n*FR + e0)*CC);
  for (int i = tid; i < ne*16; i += 256) xs4[i] = x1src[i];
  float4* hq4 = (float4*)hqs;
  const float4* hqsrc = (const float4*)(g_hq + ((size_t)n*FR + e0)*CPP);
  for (int i = tid; i < ne*4; i += 256) hq4[i] = hqsrc[i];
  __syncthreads();

  const int wid = tid >> 5, lane = tid & 31;
  // expand + silu + residual for all ne rows (f32x2)
  {
    const int c = tid & 63, rowg = tid >> 6;
    ull ew2[8];
    #pragma unroll
    for (int j = 0; j < 8; ++j)
      ew2[j] = pk2(ewt[(2*j)*64 + c], ewt[(2*j+1)*64 + c]);
    const float ebv = par[c];
    for (int r = rowg; r < ne; r += 4) {
      longlong2 q0 = *(const longlong2*)(hqs + r*16);
      longlong2 q1 = *(const longlong2*)(hqs + r*16 + 4);
      longlong2 q2 = *(const longlong2*)(hqs + r*16 + 8);
      longlong2 q3 = *(const longlong2*)(hqs + r*16 + 12);
      ull acc2 = pk2(ebv, 0.f);
      ffma2(acc2, (ull)q0.x, ew2[0]); ffma2(acc2, (ull)q0.y, ew2[1]);
      ffma2(acc2, (ull)q1.x, ew2[2]); ffma2(acc2, (ull)q1.y, ew2[3]);
      ffma2(acc2, (ull)q2.x, ew2[4]); ffma2(acc2, (ull)q2.y, ew2[5]);
      ffma2(acc2, (ull)q3.x, ew2[6]); ffma2(acc2, (ull)q3.y, ew2[7]);
      float alo, ahi; upk2(alo, ahi, acc2);
      float acc = alo + ahi;
      float sv = acc * (1.f/(1.f+__expf(-acc)));
      xs[r*64+c] += sv;
    }
  }
  __syncthreads();

  // LN over all ne rows -> ys
  for (int r = wid; r < ne; r += 8) {
    float v0 = xs[r*64+lane], v1 = xs[r*64+lane+32];
    float s = v0+v1, q = v0*v0+v1*v1;
    WRED2(s,q)
    float m = s*(1.f/64.f);
    float rr = rsqrtf(fmaxf(q*(1.f/64.f)-m*m, 0.f)+LN_EPS);
    ys[r*64+lane]    = (v0-m)*rr*par[64+lane] + par[128+lane];
    ys[r*64+lane+32] = (v1-m)*rr*par[96+lane] + par[160+lane];
  }
  __syncthreads();

  // conv #2 (f32x2) + leaky + residual, store to [B,FR,T,C]
  {
    const int c = tid & 63, rowg = tid >> 6;
    const int sub = (nf + 3) >> 2;
    const int fs = f0 + rowg*sub, fe = min(f1, fs + sub);
    const int gb = c & 56;
    ull w2[12];
    #pragma unroll
    for (int j = 0; j < 12; ++j)
      w2[j] = pk2(wc[(2*j)*64 + c], wc[(2*j+1)*64 + c]);
    const float cb = par[192+c];
    ull rm2[4], r02[4], rp2[4];
    LDROWU(fs-1, rm2)
    LDROWU(fs,   r02)
    float* obase = out + ((size_t)b*FR*TT + t)*CC;
    for (int f = fs; f < fe; ++f) {
      LDROWU(f+1, rp2)
      ull acc2 = pk2(cb, 0.f);
      #pragma unroll
      for (int q = 0; q < 4; ++q) {
        ffma2(acc2, rm2[q], w2[q]);
        ffma2(acc2, r02[q], w2[4+q]);
        ffma2(acc2, rp2[q], w2[8+q]);
      }
      float alo, ahi; upk2(alo, ahi, acc2);
      float acc = alo + ahi;
      float v = xs[(f-e0)*64+c] + (acc >= 0.f ? acc : alpha*acc);
      obase[(size_t)f*TT*CC + c] = v;
      #pragma unroll
      for (int j = 0; j < 4; ++j) { rm2[j] = r02[j]; r02[j] = rp2[j]; }
    }
  }
}

// ---------------------------------------------------------------------------
extern "C" void kernel_launch(void* const* d_in, const int* in_sizes, int n_in,
                              void* d_out, int out_size)
{
  const float* h     = (const float*)d_in[0];
  const float* fc1g  = (const float*)d_in[1];
  const float* fc1b  = (const float*)d_in[2];
  const float* fc1w  = (const float*)d_in[3];
  const float* fc1cb = (const float*)d_in[4];
  const float* fc1a  = (const float*)d_in[5];
  const float* fblg  = (const float*)d_in[6];
  const float* fblb  = (const float*)d_in[7];
  const float* redw  = (const float*)d_in[8];
  const float* redb  = (const float*)d_in[9];
  const float* fW    = (const float*)d_in[10];
  const float* fB    = (const float*)d_in[11];
  const float* expw  = (const float*)d_in[12];
  const float* expb  = (const float*)d_in[13];
  const float* fc2g  = (const float*)d_in[14];
  const float* fc2b  = (const float*)d_in[15];
  const float* fc2w  = (const float*)d_in[16];
  const float* fc2cb = (const float*)d_in[17];
  const float* fc2a  = (const float*)d_in[18];
  float* out = (float*)d_out;

  const int SM1 = (67*64 + 67*64 + 24*CC + CC*CPP + 336) * 4;
  const int SM3 = (67*64 + 67*64 + 67*CPP + 24*CC + CPP*CC + 256) * 4;
  cudaFuncSetAttribute(k_freq1, cudaFuncAttributeMaxDynamicSharedMemorySize, SM1);
  cudaFuncSetAttribute(k_freq2, cudaFuncAttributeMaxDynamicSharedMemorySize, SM3);

  dim3 g1(NN, 4);
  k_freq1<<<g1, 256, SM1>>>(h, fc1g, fc1b, fc1w, fc1cb, fc1a,
                            fblg, fblb, redw, redb);
  dim3 gg((NN+127)/128, (FR+63)/64, CPP);
  k_fgemm<<<gg, 256>>>(fW, fB);
  dim3 g3(NN, 4);
  k_freq2<<<g3, 256, SM3>>>(out, expw, expb, fc2g, fc2b, fc2w, fc2cb, fc2a);
}

// round 8
// speedup vs baseline: 2.9373x; 1.0696x over previous
#include <cuda_runtime.h>
#include <math.h>

#define BB 8
#define FR 257
#define FRP 260
#define TT 300
#define CC 64
#define CPP 16
#define NN (BB*TT)              /* 2400 */
#define NFP ((size_t)NN*FRP)
#define LN_EPS 1e-5f
#define CH 65
#define KC 32
#define XSS 68                  /* xs/ys row stride (floats) */

// Scratch (device globals: allocation-free per harness rules)
__device__ float g_x1[(size_t)NN*FR*CC];    // stage-1 output  [n][f][c]
__device__ float g_hp[(size_t)CPP*NN*FRP];  // reduced hidden  [p][n][fpad]
__device__ float g_hq[(size_t)NN*FR*CPP];   // fW GEMM output  [n][f][p]

typedef unsigned long long ull;

__device__ __forceinline__ ull pk2(float lo, float hi) {
  ull d; asm("mov.b64 %0, {%1,%2};" : "=l"(d) : "f"(lo), "f"(hi)); return d;
}
__device__ __forceinline__ void ffma2(ull& d, ull a, ull b) {
  asm("fma.rn.f32x2 %0, %1, %2, %0;" : "+l"(d) : "l"(a), "l"(b));
}
__device__ __forceinline__ void upk2(float& lo, float& hi, ull v) {
  asm("mov.b64 {%0,%1}, %2;" : "=f"(lo), "=f"(hi) : "l"(v));
}
__device__ __forceinline__ float to_tf32(float x) {
  float y;
  asm("cvt.rna.tf32.f32 %0, %1;" : "=f"(y) : "f"(x));
  return y;
}
#define MMA_TF32(ac, a0,a1,a2,a3, b0,b1) \
  asm volatile("mma.sync.aligned.m16n8k8.row.col.f32.tf32.tf32.f32 " \
    "{%0,%1,%2,%3},{%4,%5,%6,%7},{%8,%9},{%0,%1,%2,%3};" \
    : "+f"((ac)[0]), "+f"((ac)[1]), "+f"((ac)[2]), "+f"((ac)[3]) \
    : "r"(a0), "r"(a1), "r"(a2), "r"(a3), "r"(b0), "r"(b1))

// Load one 8-wide group row of ys as 4 ulls (global index F, zero outside).
#define LDROWU(F, R) { \
  if ((unsigned)(F) < (unsigned)FR) { int _lr = (F) - e0; \
    longlong2 _a = *(const longlong2*)(ys + _lr*XSS + gb); \
    longlong2 _b = *(const longlong2*)(ys + _lr*XSS + gb + 4); \
    (R)[0]=(ull)_a.x;(R)[1]=(ull)_a.y;(R)[2]=(ull)_b.x;(R)[3]=(ull)_b.y; \
  } else { \
    _Pragma("unroll") for (int _j=0;_j<4;_j++) (R)[_j]=0ull; \
  } }

#define WRED2(S,Q) { _Pragma("unroll") for (int _o=16;_o;_o>>=1){ \
  (S) += __shfl_xor_sync(0xffffffffu,(S),_o); \
  (Q) += __shfl_xor_sync(0xffffffffu,(Q),_o);} }

// ---------------------------------------------------------------------------
// K1: freq_conv #1 + LN2 + MMA reduce-to-CPP   (CTA = (n, F-chunk))
// ---------------------------------------------------------------------------
__global__ __launch_bounds__(256, 4) void k_freq1(
    const float* __restrict__ h,
    const float* __restrict__ g1, const float* __restrict__ b1,
    const float* __restrict__ w1, const float* __restrict__ cb1,
    const float* __restrict__ a1,
    const float* __restrict__ fg, const float* __restrict__ fbv,
    const float* __restrict__ rw_, const float* __restrict__ rb_)
{
  extern __shared__ float sm[];
  float* xs  = sm;              // [67*68]
  float* ys  = xs + 67*XSS;     // [80*68]  LN1 out, later LN2 out (tf32)
  float* wc  = ys + 80*XSS;     // [24*64]
  float* rwT = wc + 24*CC;      // [64*17]  tf32 [c][p]
  float* par = rwT + 64*17;     // g1|b1|cb|fg|fb (64 each) + rb(16)

  const int tid = threadIdx.x;
  const int n = blockIdx.x;
  const int b = n / TT, t = n % TT;
  const int f0 = blockIdx.y * CH;
  const int f1 = min(FR, f0 + CH);
  const int nf = f1 - f0;
  const int e0 = (f0 > 0) ? f0 - 1 : 0;
  const int e1 = (f1 < FR) ? f1 + 1 : FR;
  const int ne = e1 - e0;

  if (tid < CC) {
    par[tid]     = g1[tid];  par[64+tid]  = b1[tid];  par[128+tid] = cb1[tid];
    par[192+tid] = fg[tid];  par[256+tid] = fbv[tid];
  }
  if (tid >= 64 && tid < 64+CPP) par[320 + (tid-64)] = rb_[tid-64];
  for (int i = tid; i < 24*CC; i += 256) {
    int c = i & 63, kk = i >> 6, k = kk >> 3, ci = kk & 7;
    wc[i] = w1[c*24 + ci*3 + k];
  }
  for (int i = tid; i < CC*CPP; i += 256) {
    int c = i >> 4, p = i & 15;
    rwT[c*17 + p] = to_tf32(rw_[p*64 + c]);
  }

  const float alpha = __ldg(a1);
  const float* hbase = h + ((size_t)b*FR*TT + t)*CC;
  for (int i = tid; i < ne*16; i += 256) {
    int r = i >> 4, q = i & 15;
    *(float4*)(xs + r*XSS + q*4) =
        ((const float4*)(hbase + (size_t)(e0+r)*TT*CC))[q];
  }
  __syncthreads();

  const int wid = tid >> 5, lane = tid & 31;
  // LN1 over all ne rows -> ys
  for (int r = wid; r < ne; r += 8) {
    float v0 = xs[r*XSS+lane], v1 = xs[r*XSS+lane+32];
    float s = v0+v1, q = v0*v0+v1*v1;
    WRED2(s,q)
    float m = s*(1.f/64.f);
    float rr = rsqrtf(fmaxf(q*(1.f/64.f)-m*m, 0.f)+LN_EPS);
    ys[r*XSS+lane]    = (v0-m)*rr*par[lane]    + par[64+lane];
    ys[r*XSS+lane+32] = (v1-m)*rr*par[32+lane] + par[96+lane];
  }
  __syncthreads();

  // grouped conv (K=3, G=8) sliding window (f32x2) + leaky + residual
  {
    const int c = tid & 63, rowg = tid >> 6;
    const int sub = (nf + 3) >> 2;
    const int fs = f0 + rowg*sub, fe = min(f1, fs + sub);
    const int gb = c & 56;
    ull w2[12];
    #pragma unroll
    for (int j = 0; j < 12; ++j)
      w2[j] = pk2(wc[(2*j)*64 + c], wc[(2*j+1)*64 + c]);
    const float cb = par[128+c];
    ull rm2[4], r02[4], rp2[4];
    LDROWU(fs-1, rm2)
    LDROWU(fs,   r02)
    float* x1dst = g_x1 + (size_t)n*FR*CC;
    for (int f = fs; f < fe; ++f) {
      LDROWU(f+1, rp2)
      ull acc2 = pk2(cb, 0.f);
      #pragma unroll
      for (int q = 0; q < 4; ++q) {
        ffma2(acc2, rm2[q], w2[q]);
        ffma2(acc2, r02[q], w2[4+q]);
        ffma2(acc2, rp2[q], w2[8+q]);
      }
      float alo, ahi; upk2(alo, ahi, acc2);
      float acc = alo + ahi;
      int le = f - e0;
      float v = xs[le*XSS+c] + (acc >= 0.f ? acc : alpha*acc);
      xs[le*XSS+c] = v;
      x1dst[(size_t)f*64+c] = v;
      #pragma unroll
      for (int j = 0; j < 4; ++j) { rm2[j] = r02[j]; r02[j] = rp2[j]; }
    }
  }
  __syncthreads();

  // LN2 -> ys rows 0..nf-1 (tf32-converted, stride XSS)
  for (int fo = wid; fo < nf; fo += 8) {
    int le = fo + (e0 < f0);
    float v0 = xs[le*XSS+lane], v1 = xs[le*XSS+lane+32];
    float s = v0+v1, q = v0*v0+v1*v1;
    WRED2(s,q)
    float m = s*(1.f/64.f);
    float rr = rsqrtf(fmaxf(q*(1.f/64.f)-m*m, 0.f)+LN_EPS);
    ys[fo*XSS+lane]    = to_tf32((v0-m)*rr*par[192+lane] + par[256+lane]);
    ys[fo*XSS+lane+32] = to_tf32((v1-m)*rr*par[224+lane] + par[288+lane]);
  }
  __syncthreads();

  // MMA reduce: warp w (0..4) handles f-tile w*16, both p-tiles of 8
  if (wid < 5) {
    const int grp = lane >> 2, tig = lane & 3;
    const int fr0 = wid*16;
    float acc[2][4] = {{0.f,0.f,0.f,0.f},{0.f,0.f,0.f,0.f}};
    #pragma unroll
    for (int kc = 0; kc < 8; ++kc) {
      const int cc = kc*8;
      unsigned a0 = __float_as_uint(ys[(fr0+grp)*XSS + cc + tig]);
      unsigned a1 = __float_as_uint(ys[(fr0+grp+8)*XSS + cc + tig]);
      unsigned a2 = __float_as_uint(ys[(fr0+grp)*XSS + cc + tig + 4]);
      unsigned a3 = __float_as_uint(ys[(fr0+grp+8)*XSS + cc + tig + 4]);
      #pragma unroll
      for (int nt = 0; nt < 2; ++nt) {
        unsigned b0 = __float_as_uint(rwT[(cc+tig)*17 + nt*8 + grp]);
        unsigned b1 = __float_as_uint(rwT[(cc+tig+4)*17 + nt*8 + grp]);
        MMA_TF32(acc[nt], a0,a1,a2,a3, b0,b1);
      }
    }
    #pragma unroll
    for (int nt = 0; nt < 2; ++nt)
      #pragma unroll
      for (int q = 0; q < 4; ++q) {
        int frow = fr0 + grp + ((q >> 1) << 3);
        int p = nt*8 + 2*tig + (q & 1);
        if (frow < nf) {
          float v = acc[nt][q] + par[320+p];
          g_hp[(size_t)p*NFP + (size_t)n*FRP + f0 + frow] = v/(1.f+__expf(-v));
        }
      }
  }
}

// ---------------------------------------------------------------------------
// K2: per-channel GEMM  hq[n,g,p] = sum_f hp[p,n,f] * fW[p,g,f] + fB[p,g]
//     tf32 mma.sync m16n8k8, 128x64 CTA tile, warps 4x2 of 32x32
// ---------------------------------------------------------------------------
__global__ __launch_bounds__(256) void k_fgemm(const float* __restrict__ fW,
                                               const float* __restrict__ fB)
{
  __shared__ float As[128*36];
  __shared__ float Bs[64*36];
  __shared__ float fBs[64];
  const int p  = blockIdx.z;
  const int n0 = blockIdx.x * 128, g0 = blockIdx.y * 64;
  const float* A  = g_hp + (size_t)p*NFP;      // [NN][FRP]
  const float* Bw = fW   + (size_t)p*FR*FR;    // [FR(g)][FR(f)]
  const int tid = threadIdx.x;
  const int lane = tid & 31, wid = tid >> 5;
  const int wm = (wid & 3) * 32, wn = (wid >> 2) * 32;
  const int grp = lane >> 2, tig = lane & 3;
  if (tid < 64) fBs[tid] = (g0+tid < FR) ? fB[p*FR + g0 + tid] : 0.f;

  float acc[2][4][4];
  #pragma unroll
  for (int i = 0; i < 2; ++i)
    #pragma unroll
    for (int j = 0; j < 4; ++j)
      #pragma unroll
      for (int q = 0; q < 4; ++q) acc[i][j][q] = 0.f;

  for (int ft = 0; ft < FR; ft += KC) {
    #pragma unroll
    for (int j = 0; j < 4; ++j) {
      int u = tid + j*256;
      int row = u >> 3, kq = u & 7;
      int nn = n0 + row, fb = ft + kq*4;
      float4 v; v.x=v.y=v.z=v.w=0.f;
      if (nn < NN) {
        if (fb + 3 < FR) v = *(const float4*)&A[(size_t)nn*FRP + fb];
        else {
          if (fb   < FR) v.x = A[(size_t)nn*FRP + fb];
          if (fb+1 < FR) v.y = A[(size_t)nn*FRP + fb+1];
          if (fb+2 < FR) v.z = A[(size_t)nn*FRP + fb+2];
          if (fb+3 < FR) v.w = A[(size_t)nn*FRP + fb+3];
        }
      }
      v.x = to_tf32(v.x); v.y = to_tf32(v.y); v.z = to_tf32(v.z); v.w = to_tf32(v.w);
      *(float4*)&As[row*36 + kq*4] = v;
    }
    #pragma unroll
    for (int j = 0; j < 8; ++j) {
      int u = tid + j*256;
      int row = u >> 5, k = u & 31;
      int gg = g0 + row, ff = ft + k;
      float v = (gg < FR && ff < FR) ? Bw[(size_t)gg*FR + ff] : 0.f;
      Bs[row*36 + k] = to_tf32(v);
    }
    __syncthreads();
    #pragma unroll
    for (int k8 = 0; k8 < 4; ++k8) {
      const int col = k8*8 + tig;
      unsigned a[2][4];
      #pragma unroll
      for (int mt = 0; mt < 2; ++mt) {
        int r = wm + mt*16 + grp;
        a[mt][0] = __float_as_uint(As[r*36 + col]);
        a[mt][1] = __float_as_uint(As[(r+8)*36 + col]);
        a[mt][2] = __float_as_uint(As[r*36 + col + 4]);
        a[mt][3] = __float_as_uint(As[(r+8)*36 + col + 4]);
      }
      #pragma unroll
      for (int nt = 0; nt < 4; ++nt) {
        int rb = wn + nt*8 + grp;
        unsigned b0 = __float_as_uint(Bs[rb*36 + col]);
        unsigned b1 = __float_as_uint(Bs[rb*36 + col + 4]);
        #pragma unroll
        for (int mt = 0; mt < 2; ++mt)
          MMA_TF32(acc[mt][nt], a[mt][0],a[mt][1],a[mt][2],a[mt][3], b0,b1);
      }
    }
    __syncthreads();
  }
  #pragma unroll
  for (int mt = 0; mt < 2; ++mt) {
    #pragma unroll
    for (int nt = 0; nt < 4; ++nt) {
      int r = n0 + wm + mt*16 + grp;
      int gl = wn + nt*8 + tig*2;
      int g = g0 + gl;
      #pragma unroll
      for (int q = 0; q < 4; ++q) {
        int rr = r + (q >> 1) * 8;
        int gc = g + (q & 1);
        if (rr < NN && gc < FR)
          g_hq[((size_t)rr*FR + gc)*CPP + p] = acc[mt][nt][q] + fBs[gl + (q&1)];
      }
    }
  }
}

// ---------------------------------------------------------------------------
// K3: MMA expand + silu + residual, LN, freq_conv #2, scatter to output
// ---------------------------------------------------------------------------
__global__ __launch_bounds__(256, 4) void k_freq2(
    float* __restrict__ out,
    const float* __restrict__ ew_, const float* __restrict__ eb_,
    const float* __restrict__ g2, const float* __restrict__ b2,
    const float* __restrict__ w2_, const float* __restrict__ cb2,
    const float* __restrict__ a2)
{
  extern __shared__ float sm[];
  float* xs  = sm;              // [67*68]
  float* ys  = xs + 67*XSS;     // [67*68]
  float* hqs = ys + 67*XSS;     // [80*20]  tf32
  float* wc  = hqs + 80*20;     // [24*64]
  float* ewt = wc + 24*CC;      // [64*17]  tf32 [c][p]
  float* par = ewt + 64*17;     // eb|g2|b2|cb2 (64 each)

  const int tid = threadIdx.x;
  const int n = blockIdx.x;
  const int b = n / TT, t = n % TT;
  const int f0 = blockIdx.y * CH;
  const int f1 = min(FR, f0 + CH);
  const int nf = f1 - f0;
  const int e0 = (f0 > 0) ? f0 - 1 : 0;
  const int e1 = (f1 < FR) ? f1 + 1 : FR;
  const int ne = e1 - e0;

  if (tid < CC) {
    par[tid] = eb_[tid]; par[64+tid] = g2[tid];
    par[128+tid] = b2[tid]; par[192+tid] = cb2[tid];
  }
  for (int i = tid; i < 24*CC; i += 256) {
    int c = i & 63, kk = i >> 6, k = kk >> 3, ci = kk & 7;
    wc[i] = w2_[c*24 + ci*3 + k];
  }
  for (int i = tid; i < CC*CPP; i += 256) {
    int c = i >> 4, p = i & 15;
    ewt[c*17 + p] = to_tf32(ew_[c*CPP + p]);
  }
  const float alpha = __ldg(a2);
  const float4* x1src = (const float4*)(g_x1 + ((size_t)n*FR + e0)*CC);
  for (int i = tid; i < ne*16; i += 256) {
    int r = i >> 4, q = i & 15;
    *(float4*)(xs + r*XSS + q*4) = x1src[i];
  }
  const float4* hqsrc = (const float4*)(g_hq + ((size_t)n*FR + e0)*CPP);
  for (int i = tid; i < ne*4; i += 256) {
    int r = i >> 2, q = i & 3;
    float4 v = hqsrc[i];
    v.x = to_tf32(v.x); v.y = to_tf32(v.y); v.z = to_tf32(v.z); v.w = to_tf32(v.w);
    *(float4*)(hqs + r*20 + q*4) = v;
  }
  __syncthreads();

  const int wid = tid >> 5, lane = tid & 31;
  const int grp = lane >> 2, tig = lane & 3;

  // MMA expand: warp w = c-tile w*8, 5 f-tiles of 16; then silu + residual
  {
    float acc[5][4];
    #pragma unroll
    for (int mt = 0; mt < 5; ++mt)
      #pragma unroll
      for (int q = 0; q < 4; ++q) acc[mt][q] = 0.f;
    #pragma unroll
    for (int kc = 0; kc < 2; ++kc) {
      unsigned b0 = __float_as_uint(ewt[(wid*8+grp)*17 + kc*8 + tig]);
      unsigned b1 = __float_as_uint(ewt[(wid*8+grp)*17 + kc*8 + tig + 4]);
      #pragma unroll
      for (int mt = 0; mt < 5; ++mt) {
        unsigned a0 = __float_as_uint(hqs[(mt*16+grp)*20 + kc*8 + tig]);
        unsigned a1 = __float_as_uint(hqs[(mt*16+grp+8)*20 + kc*8 + tig]);
        unsigned a2 = __float_as_uint(hqs[(mt*16+grp)*20 + kc*8 + tig + 4]);
        unsigned a3 = __float_as_uint(hqs[(mt*16+grp+8)*20 + kc*8 + tig + 4]);
        MMA_TF32(acc[mt], a0,a1,a2,a3, b0,b1);
      }
    }
    __syncthreads();  // hqs done; also orders xs += below vs staging
    #pragma unroll
    for (int mt = 0; mt < 5; ++mt)
      #pragma unroll
      for (int q = 0; q < 4; ++q) {
        int f = mt*16 + grp + ((q >> 1) << 3);
        int c = wid*8 + 2*tig + (q & 1);
        if (f < ne) {
          float v = acc[mt][q] + par[c];
          xs[f*XSS+c] += v/(1.f+__expf(-v));
        }
      }
  }
  __syncthreads();

  // LN over all ne rows -> ys
  for (int r = wid; r < ne; r += 8) {
    float v0 = xs[r*XSS+lane], v1 = xs[r*XSS+lane+32];
    float s = v0+v1, q = v0*v0+v1*v1;
    WRED2(s,q)
    float m = s*(1.f/64.f);
    float rr = rsqrtf(fmaxf(q*(1.f/64.f)-m*m, 0.f)+LN_EPS);
    ys[r*XSS+lane]    = (v0-m)*rr*par[64+lane] + par[128+lane];
    ys[r*XSS+lane+32] = (v1-m)*rr*par[96+lane] + par[160+lane];
  }
  __syncthreads();

  // conv #2 (f32x2) + leaky + residual, store to [B,FR,T,C]
  {
    const int c = tid & 63, rowg = tid >> 6;
    const int sub = (nf + 3) >> 2;
    const int fs = f0 + rowg*sub, fe = min(f1, fs + sub);
    const int gb = c & 56;
    ull w2[12];
    #pragma unroll
    for (int j = 0; j < 12; ++j)
      w2[j] = pk2(wc[(2*j)*64 + c], wc[(2*j+1)*64 + c]);
    const float cb = par[192+c];
    ull rm2[4], r02[4], rp2[4];
    LDROWU(fs-1, rm2)
    LDROWU(fs,   r02)
    float* obase = out + ((size_t)b*FR*TT + t)*CC;
    for (int f = fs; f < fe; ++f) {
      LDROWU(f+1, rp2)
      ull acc2 = pk2(cb, 0.f);
      #pragma unroll
      for (int q = 0; q < 4; ++q) {
        ffma2(acc2, rm2[q], w2[q]);
        ffma2(acc2, r02[q], w2[4+q]);
        ffma2(acc2, rp2[q], w2[8+q]);
      }
      float alo, ahi; upk2(alo, ahi, acc2);
      float acc = alo + ahi;
      float v = xs[(f-e0)*XSS+c] + (acc >= 0.f ? acc : alpha*acc);
      obase[(size_t)f*TT*CC + c] = v;
      #pragma unroll
      for (int j = 0; j < 4; ++j) { rm2[j] = r02[j]; r02[j] = rp2[j]; }
    }
  }
}

// ---------------------------------------------------------------------------
extern "C" void kernel_launch(void* const* d_in, const int* in_sizes, int n_in,
                              void* d_out, int out_size)
{
  const float* h     = (const float*)d_in[0];
  const float* fc1g  = (const float*)d_in[1];
  const float* fc1b  = (const float*)d_in[2];
  const float* fc1w  = (const float*)d_in[3];
  const float* fc1cb = (const float*)d_in[4];
  const float* fc1a  = (const float*)d_in[5];
  const float* fblg  = (const float*)d_in[6];
  const float* fblb  = (const float*)d_in[7];
  const float* redw  = (const float*)d_in[8];
  const float* redb  = (const float*)d_in[9];
  const float* fW    = (const float*)d_in[10];
  const float* fB    = (const float*)d_in[11];
  const float* expw  = (const float*)d_in[12];
  const float* expb  = (const float*)d_in[13];
  const float* fc2g  = (const float*)d_in[14];
  const float* fc2b  = (const float*)d_in[15];
  const float* fc2w  = (const float*)d_in[16];
  const float* fc2cb = (const float*)d_in[17];
  const float* fc2a  = (const float*)d_in[18];
  float* out = (float*)d_out;

  const int SM1 = (67*XSS + 80*XSS + 24*CC + 64*17 + 336) * 4;
  const int SM3 = (67*XSS + 67*XSS + 80*20 + 24*CC + 64*17 + 256) * 4;
  cudaFuncSetAttribute(k_freq1, cudaFuncAttributeMaxDynamicSharedMemorySize, SM1);
  cudaFuncSetAttribute(k_freq2, cudaFuncAttributeMaxDynamicSharedMemorySize, SM3);

  dim3 g1(NN, 4);
  k_freq1<<<g1, 256, SM1>>>(h, fc1g, fc1b, fc1w, fc1cb, fc1a,
                            fblg, fblb, redw, redb);
  dim3 gg((NN+127)/128, (FR+63)/64, CPP);
  k_fgemm<<<gg, 256>>>(fW, fB);
  dim3 g3(NN, 4);
  k_freq2<<<g3, 256, SM3>>>(out, expw, expb, fc2g, fc2b, fc2w, fc2cb, fc2a);
}

// round 9
// speedup vs baseline: 3.1516x; 1.0730x over previous
#include <cuda_runtime.h>
#include <math.h>

#define BB 8
#define FR 257
#define FRP 288                 /* padded row (9*32) for g_hp: unguarded k-tiles */
#define TT 300
#define CC 64
#define CPP 16
#define NN (BB*TT)              /* 2400 */
#define NFP ((size_t)NN*FRP)
#define LN_EPS 1e-5f
#define CH 65
#define XSS 68                  /* xs/ys row stride (floats) */

// Scratch (device globals: allocation-free; zero-initialized at module load —
// g_hp padding cols [257,288) are never written and stay exactly 0)
__device__ float g_x1[(size_t)NN*FR*CC];    // stage-1 output  [n][f][c]
__device__ float g_hp[(size_t)CPP*NN*FRP];  // reduced hidden  [p][n][fpad]
__device__ float g_hq[(size_t)NN*FR*CPP];   // fW GEMM output  [n][f][p]

typedef unsigned long long ull;

__device__ __forceinline__ ull pk2(float lo, float hi) {
  ull d; asm("mov.b64 %0, {%1,%2};" : "=l"(d) : "f"(lo), "f"(hi)); return d;
}
__device__ __forceinline__ void ffma2(ull& d, ull a, ull b) {
  asm("fma.rn.f32x2 %0, %1, %2, %0;" : "+l"(d) : "l"(a), "l"(b));
}
__device__ __forceinline__ void fadd2(ull& d, ull a) {
  asm("add.rn.f32x2 %0, %0, %1;" : "+l"(d) : "l"(a));
}
__device__ __forceinline__ void upk2(float& lo, float& hi, ull v) {
  asm("mov.b64 {%0,%1}, %2;" : "=f"(lo), "=f"(hi) : "l"(v));
}
__device__ __forceinline__ float to_tf32(float x) {
  float y;
  asm("cvt.rna.tf32.f32 %0, %1;" : "=f"(y) : "f"(x));
  return y;
}
#define MMA_TF32(ac, a0,a1,a2,a3, b0,b1) \
  asm volatile("mma.sync.aligned.m16n8k8.row.col.f32.tf32.tf32.f32 " \
    "{%0,%1,%2,%3},{%4,%5,%6,%7},{%8,%9},{%0,%1,%2,%3};" \
    : "+f"((ac)[0]), "+f"((ac)[1]), "+f"((ac)[2]), "+f"((ac)[3]) \
    : "r"(a0), "r"(a1), "r"(a2), "r"(a3), "r"(b0), "r"(b1))

// Load one 8-wide group row of ys as 4 ulls (global index F, zero outside).
#define LDROWU(F, R) { \
  if ((unsigned)(F) < (unsigned)FR) { int _lr = (F) - e0; \
    longlong2 _a = *(const longlong2*)(ys + _lr*XSS + gb); \
    longlong2 _b = *(const longlong2*)(ys + _lr*XSS + gb + 4); \
    (R)[0]=(ull)_a.x;(R)[1]=(ull)_a.y;(R)[2]=(ull)_b.x;(R)[3]=(ull)_b.y; \
  } else { \
    _Pragma("unroll") for (int _j=0;_j<4;_j++) (R)[_j]=0ull; \
  } }

// 3-chain grouped-conv step: rm2/r02/rp2 are the 3 tap rows.
#define CONV3(ACCOUT) { \
  ull _ca = pk2(cb, 0.f), _cb = 0ull, _cc = 0ull; \
  _Pragma("unroll") \
  for (int _q = 0; _q < 4; ++_q) { \
    ffma2(_ca, rm2[_q], w2[_q]); \
    ffma2(_cb, r02[_q], w2[4+_q]); \
    ffma2(_cc, rp2[_q], w2[8+_q]); \
  } \
  fadd2(_ca, _cb); fadd2(_ca, _cc); \
  float _lo, _hi; upk2(_lo, _hi, _ca); \
  (ACCOUT) = _lo + _hi; }

#define WRED2(S,Q) { _Pragma("unroll") for (int _o=16;_o;_o>>=1){ \
  (S) += __shfl_xor_sync(0xffffffffu,(S),_o); \
  (Q) += __shfl_xor_sync(0xffffffffu,(Q),_o);} }

// ---------------------------------------------------------------------------
// K1: freq_conv #1 + LN2 + MMA reduce-to-CPP   (CTA = (n, F-chunk))
// ---------------------------------------------------------------------------
__global__ __launch_bounds__(256, 4) void k_freq1(
    const float* __restrict__ h,
    const float* __restrict__ g1, const float* __restrict__ b1,
    const float* __restrict__ w1, const float* __restrict__ cb1,
    const float* __restrict__ a1,
    const float* __restrict__ fg, const float* __restrict__ fbv,
    const float* __restrict__ rw_, const float* __restrict__ rb_)
{
  extern __shared__ float sm[];
  float* xs  = sm;              // [67*68]
  float* ys  = xs + 67*XSS;     // [80*68]  LN1 out, later LN2 out (tf32)
  float* wc  = ys + 80*XSS;     // [24*64]
  float* rwT = wc + 24*CC;      // [64*17]  tf32 [c][p]
  float* par = rwT + 64*17;     // g1|b1|cb|fg|fb (64 each) + rb(16)

  const int tid = threadIdx.x;
  const int n = blockIdx.x;
  const int b = n / TT, t = n % TT;
  const int f0 = blockIdx.y * CH;
  const int f1 = min(FR, f0 + CH);
  const int nf = f1 - f0;
  const int e0 = (f0 > 0) ? f0 - 1 : 0;
  const int e1 = (f1 < FR) ? f1 + 1 : FR;
  const int ne = e1 - e0;

  if (tid < CC) {
    par[tid]     = g1[tid];  par[64+tid]  = b1[tid];  par[128+tid] = cb1[tid];
    par[192+tid] = fg[tid];  par[256+tid] = fbv[tid];
  }
  if (tid >= 64 && tid < 64+CPP) par[320 + (tid-64)] = rb_[tid-64];
  for (int i = tid; i < 24*CC; i += 256) {
    int c = i & 63, kk = i >> 6, k = kk >> 3, ci = kk & 7;
    wc[i] = w1[c*24 + ci*3 + k];
  }
  for (int i = tid; i < CC*CPP; i += 256) {
    int c = i >> 4, p = i & 15;
    rwT[c*17 + p] = to_tf32(rw_[p*64 + c]);
  }

  const float alpha = __ldg(a1);
  const float* hbase = h + ((size_t)b*FR*TT + t)*CC;
  for (int i = tid; i < ne*16; i += 256) {
    int r = i >> 4, q = i & 15;
    *(float4*)(xs + r*XSS + q*4) =
        ((const float4*)(hbase + (size_t)(e0+r)*TT*CC))[q];
  }
  __syncthreads();

  const int wid = tid >> 5, lane = tid & 31;
  // LN1 over all ne rows -> ys
  for (int r = wid; r < ne; r += 8) {
    float v0 = xs[r*XSS+lane], v1 = xs[r*XSS+lane+32];
    float s = v0+v1, q = v0*v0+v1*v1;
    WRED2(s,q)
    float m = s*(1.f/64.f);
    float rr = rsqrtf(fmaxf(q*(1.f/64.f)-m*m, 0.f)+LN_EPS);
    ys[r*XSS+lane]    = (v0-m)*rr*par[lane]    + par[64+lane];
    ys[r*XSS+lane+32] = (v1-m)*rr*par[32+lane] + par[96+lane];
  }
  __syncthreads();

  // grouped conv (K=3, G=8) sliding window, 3 indep. chains + leaky + residual
  {
    const int c = tid & 63, rowg = tid >> 6;
    const int sub = (nf + 3) >> 2;
    const int fs = f0 + rowg*sub, fe = min(f1, fs + sub);
    const int gb = c & 56;
    ull w2[12];
    #pragma unroll
    for (int j = 0; j < 12; ++j)
      w2[j] = pk2(wc[(2*j)*64 + c], wc[(2*j+1)*64 + c]);
    const float cb = par[128+c];
    ull rm2[4], r02[4], rp2[4];
    LDROWU(fs-1, rm2)
    LDROWU(fs,   r02)
    float* x1dst = g_x1 + (size_t)n*FR*CC;
    for (int f = fs; f < fe; ++f) {
      LDROWU(f+1, rp2)
      float acc; CONV3(acc)
      int le = f - e0;
      float v = xs[le*XSS+c] + (acc >= 0.f ? acc : alpha*acc);
      xs[le*XSS+c] = v;
      x1dst[(size_t)f*64+c] = v;
      #pragma unroll
      for (int j = 0; j < 4; ++j) { rm2[j] = r02[j]; r02[j] = rp2[j]; }
    }
  }
  __syncthreads();

  // LN2 -> ys rows 0..nf-1 (tf32-converted, stride XSS)
  for (int fo = wid; fo < nf; fo += 8) {
    int le = fo + (e0 < f0);
    float v0 = xs[le*XSS+lane], v1 = xs[le*XSS+lane+32];
    float s = v0+v1, q = v0*v0+v1*v1;
    WRED2(s,q)
    float m = s*(1.f/64.f);
    float rr = rsqrtf(fmaxf(q*(1.f/64.f)-m*m, 0.f)+LN_EPS);
    ys[fo*XSS+lane]    = to_tf32((v0-m)*rr*par[192+lane] + par[256+lane]);
    ys[fo*XSS+lane+32] = to_tf32((v1-m)*rr*par[224+lane] + par[288+lane]);
  }
  __syncthreads();

  // MMA reduce: warp w (0..4) handles f-tile w*16, both p-tiles of 8
  if (wid < 5) {
    const int grp = lane >> 2, tig = lane & 3;
    const int fr0 = wid*16;
    float acc[2][4] = {{0.f,0.f,0.f,0.f},{0.f,0.f,0.f,0.f}};
    #pragma unroll
    for (int kc = 0; kc < 8; ++kc) {
      const int cc = kc*8;
      unsigned a0 = __float_as_uint(ys[(fr0+grp)*XSS + cc + tig]);
      unsigned a1 = __float_as_uint(ys[(fr0+grp+8)*XSS + cc + tig]);
      unsigned a2 = __float_as_uint(ys[(fr0+grp)*XSS + cc + tig + 4]);
      unsigned a3 = __float_as_uint(ys[(fr0+grp+8)*XSS + cc + tig + 4]);
      #pragma unroll
      for (int nt = 0; nt < 2; ++nt) {
        unsigned b0 = __float_as_uint(rwT[(cc+tig)*17 + nt*8 + grp]);
        unsigned b1 = __float_as_uint(rwT[(cc+tig+4)*17 + nt*8 + grp]);
        MMA_TF32(acc[nt], a0,a1,a2,a3, b0,b1);
      }
    }
    #pragma unroll
    for (int nt = 0; nt < 2; ++nt)
      #pragma unroll
      for (int q = 0; q < 4; ++q) {
        int frow = fr0 + grp + ((q >> 1) << 3);
        int p = nt*8 + 2*tig + (q & 1);
        if (frow < nf) {
          float v = acc[nt][q] + par[320+p];
          g_hp[(size_t)p*NFP + (size_t)n*FRP + f0 + frow] = v/(1.f+__expf(-v));
        }
      }
  }
}

// ---------------------------------------------------------------------------
// K2: per-channel GEMM  hq[n,g,p] = sum_f hp[p,n,f] * fW[p,g,f] + fB[p,g]
//     tf32 mma m16n8k8 (raw-f32 truncation), 128x64 tile, reg-prefetch 2-buf
// ---------------------------------------------------------------------------
#define K2_LOAD(FT) { \
  _Pragma("unroll") for (int j = 0; j < 4; ++j) { \
    int u = tid + j*256; int row = u >> 3, kq = u & 7; \
    int nn = n0 + row; \
    ra[j] = make_float4(0.f,0.f,0.f,0.f); \
    if (nn < NN) ra[j] = *(const float4*)&A[(size_t)nn*FRP + (FT) + kq*4]; \
  } \
  _Pragma("unroll") for (int j = 0; j < 8; ++j) { \
    int u = tid + j*256; int row = u >> 5, k = u & 31; \
    int gg = g0 + row, ff = (FT) + k; \
    rb[j] = (gg < FR && ff < FR) ? Bw[(size_t)gg*FR + ff] : 0.f; \
  } }

#define K2_STORE(BUF) { \
  _Pragma("unroll") for (int j = 0; j < 4; ++j) { \
    int u = tid + j*256; int row = u >> 3, kq = u & 7; \
    *(float4*)&As[BUF][row*36 + kq*4] = ra[j]; \
  } \
  _Pragma("unroll") for (int j = 0; j < 8; ++j) { \
    int u = tid + j*256; int row = u >> 5, k = u & 31; \
    Bs[BUF][row*36 + k] = rb[j]; \
  } }

__global__ __launch_bounds__(256) void k_fgemm(const float* __restrict__ fW,
                                               const float* __restrict__ fB)
{
  __shared__ float As[2][128*36];
  __shared__ float Bs[2][64*36];
  __shared__ float fBs[64];
  const int p  = blockIdx.z;
  const int n0 = blockIdx.x * 128, g0 = blockIdx.y * 64;
  const float* A  = g_hp + (size_t)p*NFP;      // [NN][FRP] (pad cols are 0)
  const float* Bw = fW   + (size_t)p*FR*FR;    // [FR(g)][FR(f)]
  const int tid = threadIdx.x;
  const int lane = tid & 31, wid = tid >> 5;
  const int wm = (wid & 3) * 32, wn = (wid >> 2) * 32;
  const int grp = lane >> 2, tig = lane & 3;
  if (tid < 64) fBs[tid] = (g0+tid < FR) ? fB[p*FR + g0 + tid] : 0.f;

  float acc[2][4][4];
  #pragma unroll
  for (int i = 0; i < 2; ++i)
    #pragma unroll
    for (int j = 0; j < 4; ++j)
      #pragma unroll
      for (int q = 0; q < 4; ++q) acc[i][j][q] = 0.f;

  float4 ra[4]; float rb[8];
  K2_LOAD(0)
  K2_STORE(0)
  __syncthreads();

  for (int it = 0; it < 9; ++it) {
    if (it < 8) { K2_LOAD((it+1)*32) }
    const int cur = it & 1;
    #pragma unroll
    for (int k8 = 0; k8 < 4; ++k8) {
      const int col = k8*8 + tig;
      unsigned a[2][4];
      #pragma unroll
      for (int mt = 0; mt < 2; ++mt) {
        int r = wm + mt*16 + grp;
        a[mt][0] = __float_as_uint(As[cur][r*36 + col]);
        a[mt][1] = __float_as_uint(As[cur][(r+8)*36 + col]);
        a[mt][2] = __float_as_uint(As[cur][r*36 + col + 4]);
        a[mt][3] = __float_as_uint(As[cur][(r+8)*36 + col + 4]);
      }
      #pragma unroll
      for (int nt = 0; nt < 4; ++nt) {
        int rbw = wn + nt*8 + grp;
        unsigned b0 = __float_as_uint(Bs[cur][rbw*36 + col]);
        unsigned b1 = __float_as_uint(Bs[cur][rbw*36 + col + 4]);
        #pragma unroll
        for (int mt = 0; mt < 2; ++mt)
          MMA_TF32(acc[mt][nt], a[mt][0],a[mt][1],a[mt][2],a[mt][3], b0,b1);
      }
    }
    if (it < 8) {
      K2_STORE((it+1) & 1)
      __syncthreads();
    }
  }

  #pragma unroll
  for (int mt = 0; mt < 2; ++mt) {
    #pragma unroll
    for (int nt = 0; nt < 4; ++nt) {
      int r = n0 + wm + mt*16 + grp;
      int gl = wn + nt*8 + tig*2;
      int g = g0 + gl;
      #pragma unroll
      for (int q = 0; q < 4; ++q) {
        int rr = r + (q >> 1) * 8;
        int gc = g + (q & 1);
        if (rr < NN && gc < FR)
          g_hq[((size_t)rr*FR + gc)*CPP + p] = acc[mt][nt][q] + fBs[gl + (q&1)];
      }
    }
  }
}

// ---------------------------------------------------------------------------
// K3: MMA expand + silu + residual, LN, freq_conv #2, scatter to output
// ---------------------------------------------------------------------------
__global__ __launch_bounds__(256, 4) void k_freq2(
    float* __restrict__ out,
    const float* __restrict__ ew_, const float* __restrict__ eb_,
    const float* __restrict__ g2, const float* __restrict__ b2,
    const float* __restrict__ w2_, const float* __restrict__ cb2,
    const float* __restrict__ a2)
{
  extern __shared__ float sm[];
  float* xs  = sm;              // [67*68]
  float* ys  = xs + 67*XSS;     // [67*68]
  float* hqs = ys + 67*XSS;     // [80*20]  tf32
  float* wc  = hqs + 80*20;     // [24*64]
  float* ewt = wc + 24*CC;      // [64*17]  tf32 [c][p]
  float* par = ewt + 64*17;     // eb|g2|b2|cb2 (64 each)

  const int tid = threadIdx.x;
  const int n = blockIdx.x;
  const int b = n / TT, t = n % TT;
  const int f0 = blockIdx.y * CH;
  const int f1 = min(FR, f0 + CH);
  const int nf = f1 - f0;
  const int e0 = (f0 > 0) ? f0 - 1 : 0;
  const int e1 = (f1 < FR) ? f1 + 1 : FR;
  const int ne = e1 - e0;

  if (tid < CC) {
    par[tid] = eb_[tid]; par[64+tid] = g2[tid];
    par[128+tid] = b2[tid]; par[192+tid] = cb2[tid];
  }
  for (int i = tid; i < 24*CC; i += 256) {
    int c = i & 63, kk = i >> 6, k = kk >> 3, ci = kk & 7;
    wc[i] = w2_[c*24 + ci*3 + k];
  }
  for (int i = tid; i < CC*CPP; i += 256) {
    int c = i >> 4, p = i & 15;
    ewt[c*17 + p] = to_tf32(ew_[c*CPP + p]);
  }
  const float alpha = __ldg(a2);
  const float4* x1src = (const float4*)(g_x1 + ((size_t)n*FR + e0)*CC);
  for (int i = tid; i < ne*16; i += 256) {
    int r = i >> 4, q = i & 15;
    *(float4*)(xs + r*XSS + q*4) = x1src[i];
  }
  const float4* hqsrc = (const float4*)(g_hq + ((size_t)n*FR + e0)*CPP);
  for (int i = tid; i < ne*4; i += 256) {
    int r = i >> 2, q = i & 3;
    float4 v = hqsrc[i];
    v.x = to_tf32(v.x); v.y = to_tf32(v.y); v.z = to_tf32(v.z); v.w = to_tf32(v.w);
    *(float4*)(hqs + r*20 + q*4) = v;
  }
  __syncthreads();

  const int wid = tid >> 5, lane = tid & 31;
  const int grp = lane >> 2, tig = lane & 3;

  // MMA expand: warp w = c-tile w*8, 5 f-tiles of 16; then silu + residual
  {
    float acc[5][4];
    #pragma unroll
    for (int mt = 0; mt < 5; ++mt)
      #pragma unroll
      for (int q = 0; q < 4; ++q) acc[mt][q] = 0.f;
    #pragma unroll
    for (int kc = 0; kc < 2; ++kc) {
      unsigned b0 = __float_as_uint(ewt[(wid*8+grp)*17 + kc*8 + tig]);
      unsigned b1 = __float_as_uint(ewt[(wid*8+grp)*17 + kc*8 + tig + 4]);
      #pragma unroll
      for (int mt = 0; mt < 5; ++mt) {
        unsigned a0 = __float_as_uint(hqs[(mt*16+grp)*20 + kc*8 + tig]);
        unsigned a1 = __float_as_uint(hqs[(mt*16+grp+8)*20 + kc*8 + tig]);
        unsigned a2 = __float_as_uint(hqs[(mt*16+grp)*20 + kc*8 + tig + 4]);
        unsigned a3 = __float_as_uint(hqs[(mt*16+grp+8)*20 + kc*8 + tig + 4]);
        MMA_TF32(acc[mt], a0,a1,a2,a3, b0,b1);
      }
    }
    __syncthreads();
    #pragma unroll
    for (int mt = 0; mt < 5; ++mt)
      #pragma unroll
      for (int q = 0; q < 4; ++q) {
        int f = mt*16 + grp + ((q >> 1) << 3);
        int c = wid*8 + 2*tig + (q & 1);
        if (f < ne) {
          float v = acc[mt][q] + par[c];
          xs[f*XSS+c] += v/(1.f+__expf(-v));
        }
      }
  }
  __syncthreads();

  // LN over all ne rows -> ys
  for (int r = wid; r < ne; r += 8) {
    float v0 = xs[r*XSS+lane], v1 = xs[r*XSS+lane+32];
    float s = v0+v1, q = v0*v0+v1*v1;
    WRED2(s,q)
    float m = s*(1.f/64.f);
    float rr = rsqrtf(fmaxf(q*(1.f/64.f)-m*m, 0.f)+LN_EPS);
    ys[r*XSS+lane]    = (v0-m)*rr*par[64+lane] + par[128+lane];
    ys[r*XSS+lane+32] = (v1-m)*rr*par[96+lane] + par[160+lane];
  }
  __syncthreads();

  // conv #2 (3-chain f32x2) + leaky + residual, store to [B,FR,T,C]
  {
    const int c = tid & 63, rowg = tid >> 6;
    const int sub = (nf + 3) >> 2;
    const int fs = f0 + rowg*sub, fe = min(f1, fs + sub);
    const int gb = c & 56;
    ull w2[12];
    #pragma unroll
    for (int j = 0; j < 12; ++j)
      w2[j] = pk2(wc[(2*j)*64 + c], wc[(2*j+1)*64 + c]);
    const float cb = par[192+c];
    ull rm2[4], r02[4], rp2[4];
    LDROWU(fs-1, rm2)
    LDROWU(fs,   r02)
    float* obase = out + ((size_t)b*FR*TT + t)*CC;
    for (int f = fs; f < fe; ++f) {
      LDROWU(f+1, rp2)
      float acc; CONV3(acc)
      float v = xs[(f-e0)*XSS+c] + (acc >= 0.f ? acc : alpha*acc);
      obase[(size_t)f*TT*CC + c] = v;
      #pragma unroll
      for (int j = 0; j < 4; ++j) { rm2[j] = r02[j]; r02[j] = rp2[j]; }
    }
  }
}

// ---------------------------------------------------------------------------
extern "C" void kernel_launch(void* const* d_in, const int* in_sizes, int n_in,
                              void* d_out, int out_size)
{
  const float* h     = (const float*)d_in[0];
  const float* fc1g  = (const float*)d_in[1];
  const float* fc1b  = (const float*)d_in[2];
  const float* fc1w  = (const float*)d_in[3];
  const float* fc1cb = (const float*)d_in[4];
  const float* fc1a  = (const float*)d_in[5];
  const float* fblg  = (const float*)d_in[6];
  const float* fblb  = (const float*)d_in[7];
  const float* redw  = (const float*)d_in[8];
  const float* redb  = (const float*)d_in[9];
  const float* fW    = (const float*)d_in[10];
  const float* fB    = (const float*)d_in[11];
  const float* expw  = (const float*)d_in[12];
  const float* expb  = (const float*)d_in[13];
  const float* fc2g  = (const float*)d_in[14];
  const float* fc2b  = (const float*)d_in[15];
  const float* fc2w  = (const float*)d_in[16];
  const float* fc2cb = (const float*)d_in[17];
  const float* fc2a  = (const float*)d_in[18];
  float* out = (float*)d_out;

  const int SM1 = (67*XSS + 80*XSS + 24*CC + 64*17 + 336) * 4;
  const int SM3 = (67*XSS + 67*XSS + 80*20 + 24*CC + 64*17 + 256) * 4;
  cudaFuncSetAttribute(k_freq1, cudaFuncAttributeMaxDynamicSharedMemorySize, SM1);
  cudaFuncSetAttribute(k_freq2, cudaFuncAttributeMaxDynamicSharedMemorySize, SM3);

  dim3 g1(NN, 4);
  k_freq1<<<g1, 256, SM1>>>(h, fc1g, fc1b, fc1w, fc1cb, fc1a,
                            fblg, fblb, redw, redb);
  dim3 gg((NN+127)/128, (FR+63)/64, CPP);
  k_fgemm<<<gg, 256>>>(fW, fB);
  dim3 g3(NN, 4);
  k_freq2<<<g3, 256, SM3>>>(out, expw, expb, fc2g, fc2b, fc2w, fc2cb, fc2a);
}

// round 10
// speedup vs baseline: 3.4233x; 1.0862x over previous
#include <cuda_runtime.h>
#include <math.h>

#define BB 8
#define FR 257
#define FRP 288                 /* padded row (9*32) for g_hp: unguarded k-tiles */
#define TT 300
#define CC 64
#define CPP 16
#define NN (BB*TT)              /* 2400 */
#define NFP ((size_t)NN*FRP)
#define LN_EPS 1e-5f
#define CH 65
#define XSS 68                  /* xs/ys row stride (floats) */

// Scratch (device globals: allocation-free; zero-initialized at module load —
// g_hp padding cols [257,288) are never written and stay exactly 0)
__device__ float g_x1[(size_t)NN*FR*CC];    // stage-1 output  [n][f][c]
__device__ float g_hp[(size_t)CPP*NN*FRP];  // reduced hidden  [p][n][fpad]
__device__ float g_hq[(size_t)NN*FR*CPP];   // fW GEMM output  [n][f][p]

__device__ __forceinline__ float to_tf32(float x) {
  float y;
  asm("cvt.rna.tf32.f32 %0, %1;" : "=f"(y) : "f"(x));
  return y;
}
#define MMA_TF32(ac, a0,a1,a2,a3, b0,b1) \
  asm volatile("mma.sync.aligned.m16n8k8.row.col.f32.tf32.tf32.f32 " \
    "{%0,%1,%2,%3},{%4,%5,%6,%7},{%8,%9},{%0,%1,%2,%3};" \
    : "+f"((ac)[0]), "+f"((ac)[1]), "+f"((ac)[2]), "+f"((ac)[3]) \
    : "r"(a0), "r"(a1), "r"(a2), "r"(a3), "r"(b0), "r"(b1))

#define WRED2(S,Q) { _Pragma("unroll") for (int _o=16;_o;_o>>=1){ \
  (S) += __shfl_xor_sync(0xffffffffu,(S),_o); \
  (Q) += __shfl_xor_sync(0xffffffffu,(Q),_o);} }

// MMA grouped conv: warp `w` = channel-group w. ysc = LN-output buffer with
// valid rows [0,ne), zero rows at -1 and [ne, 82). Output (into CODE) for
// local f in [0,nf): acc[q] + conv-bias -> leaky -> CODE(fl, c, lv).
// A row for tap kk = ysc[off + fl + kk - 1]. Requires bb[3][2] preloaded.
#define CONV_MMA(CBOFS, CODE) { \
  unsigned bb[3][2]; \
  _Pragma("unroll") \
  for (int kk = 0; kk < 3; ++kk) { \
    bb[kk][0] = __float_as_uint(wcg[((wid*3+kk)*8 + grp)*9 + tig]); \
    bb[kk][1] = __float_as_uint(wcg[((wid*3+kk)*8 + grp)*9 + tig + 4]); \
  } \
  const float cb0 = par[(CBOFS) + wid*8 + 2*tig]; \
  const float cb1 = par[(CBOFS) + wid*8 + 2*tig + 1]; \
  const int ntiles = (nf + 15) >> 4; \
  for (int mt = 0; mt < ntiles; ++mt) { \
    float acc[4] = {0.f, 0.f, 0.f, 0.f}; \
    const int fb = mt*16 + off - 1; \
    _Pragma("unroll") \
    for (int kk = 0; kk < 3; ++kk) { \
      const int r = fb + kk; \
      unsigned a0 = __float_as_uint(ysc[(r+grp)*XSS   + wid*8 + tig]); \
      unsigned a1 = __float_as_uint(ysc[(r+grp+8)*XSS + wid*8 + tig]); \
      unsigned a2 = __float_as_uint(ysc[(r+grp)*XSS   + wid*8 + tig + 4]); \
      unsigned a3 = __float_as_uint(ysc[(r+grp+8)*XSS + wid*8 + tig + 4]); \
      MMA_TF32(acc, a0,a1,a2,a3, bb[kk][0], bb[kk][1]); \
    } \
    _Pragma("unroll") \
    for (int q = 0; q < 4; ++q) { \
      const int fl = mt*16 + grp + ((q >> 1) << 3); \
      if (fl < nf) { \
        const int c = wid*8 + 2*tig + (q & 1); \
        float a = acc[q] + ((q & 1) ? cb1 : cb0); \
        float lv = (a >= 0.f) ? a : alpha*a; \
        CODE \
      } \
    } \
  } }

// ---------------------------------------------------------------------------
// K1: LN1 + MMA grouped conv #1 + LN2 (+x1 store) + MMA reduce-to-CPP
// ---------------------------------------------------------------------------
__global__ __launch_bounds__(256, 4) void k_freq1(
    const float* __restrict__ h,
    const float* __restrict__ g1, const float* __restrict__ b1,
    const float* __restrict__ w1, const float* __restrict__ cb1,
    const float* __restrict__ a1,
    const float* __restrict__ fg, const float* __restrict__ fbv,
    const float* __restrict__ rw_, const float* __restrict__ rb_)
{
  extern __shared__ float sm[];
  float* xs  = sm;              // [67*68]
  float* ysb = xs + 67*XSS;     // [83*68]  rows -1..81 of conv-view
  float* wcg = ysb + 83*XSS;    // [8g][3kk][8c'][9] tf32 conv weights
  float* rwT = wcg + 8*3*8*9;   // [64*17]  tf32 [c][p]
  float* par = rwT + 64*17;     // g1|b1|cb|fg|fb (64 each) + rb(16)
  float* ysc = ysb + XSS;       // conv-view base (row -1 = ysb row 0)

  const int tid = threadIdx.x;
  const int n = blockIdx.x;
  const int b = n / TT, t = n % TT;
  const int f0 = blockIdx.y * CH;
  const int f1 = min(FR, f0 + CH);
  const int nf = f1 - f0;
  const int e0 = (f0 > 0) ? f0 - 1 : 0;
  const int e1 = (f1 < FR) ? f1 + 1 : FR;
  const int ne = e1 - e0;
  const int off = (f0 > 0) ? 1 : 0;

  if (tid < CC) {
    par[tid]     = g1[tid];  par[64+tid]  = b1[tid];  par[128+tid] = cb1[tid];
    par[192+tid] = fg[tid];  par[256+tid] = fbv[tid];
  }
  if (tid >= 64 && tid < 64+CPP) par[320 + (tid-64)] = rb_[tid-64];
  for (int i = tid; i < 8*3*64; i += 256) {
    int g = i / 192, r = i % 192, kk = r >> 6, s = r & 63;
    int cp = s >> 3, ci = s & 7;
    wcg[((g*3+kk)*8 + cp)*9 + ci] = to_tf32(w1[(g*8+cp)*24 + ci*3 + kk]);
  }
  for (int i = tid; i < CC*CPP; i += 256) {
    int c = i >> 4, p = i & 15;
    rwT[c*17 + p] = to_tf32(rw_[p*64 + c]);
  }
  // zero conv halo rows: ysc[-1] and ysc[ne..81]
  for (int i = tid; i < XSS; i += 256) ysb[i] = 0.f;
  for (int i = tid + (ne+1)*XSS; i < 83*XSS; i += 256) ysb[i] = 0.f;

  const float alpha = __ldg(a1);
  const float* hbase = h + ((size_t)b*FR*TT + t)*CC;
  for (int i = tid; i < ne*16; i += 256) {
    int r = i >> 4, q = i & 15;
    *(float4*)(xs + r*XSS + q*4) =
        ((const float4*)(hbase + (size_t)(e0+r)*TT*CC))[q];
  }
  __syncthreads();

  const int wid = tid >> 5, lane = tid & 31;
  const int grp = lane >> 2, tig = lane & 3;

  // LN1 over all ne rows -> ysc (tf32)
  for (int r = wid; r < ne; r += 8) {
    float v0 = xs[r*XSS+lane], v1 = xs[r*XSS+lane+32];
    float s = v0+v1, q = v0*v0+v1*v1;
    WRED2(s,q)
    float m = s*(1.f/64.f);
    float rr = rsqrtf(fmaxf(q*(1.f/64.f)-m*m, 0.f)+LN_EPS);
    ysc[r*XSS+lane]    = to_tf32((v0-m)*rr*par[lane]    + par[64+lane]);
    ysc[r*XSS+lane+32] = to_tf32((v1-m)*rr*par[32+lane] + par[96+lane]);
  }
  __syncthreads();

  // MMA grouped conv + leaky + residual (update xs in place)
  CONV_MMA(128, {
    int xr = fl + off;
    xs[xr*XSS + c] += lv;
  })
  __syncthreads();

  // LN2 -> ysc rows 0..nf-1 (tf32) + coalesced x1 store
  float* x1dst = g_x1 + (size_t)n*FR*CC;
  for (int fo = wid; fo < nf; fo += 8) {
    int le = fo + off;
    float v0 = xs[le*XSS+lane], v1 = xs[le*XSS+lane+32];
    x1dst[(size_t)(f0+fo)*64 + lane]      = v0;
    x1dst[(size_t)(f0+fo)*64 + lane + 32] = v1;
    float s = v0+v1, q = v0*v0+v1*v1;
    WRED2(s,q)
    float m = s*(1.f/64.f);
    float rr = rsqrtf(fmaxf(q*(1.f/64.f)-m*m, 0.f)+LN_EPS);
    ysc[fo*XSS+lane]    = to_tf32((v0-m)*rr*par[192+lane] + par[256+lane]);
    ysc[fo*XSS+lane+32] = to_tf32((v1-m)*rr*par[224+lane] + par[288+lane]);
  }
  __syncthreads();

  // MMA reduce: warp w (0..4) handles f-tile w*16, both p-tiles of 8
  if (wid < 5) {
    const int fr0 = wid*16;
    float acc[2][4] = {{0.f,0.f,0.f,0.f},{0.f,0.f,0.f,0.f}};
    #pragma unroll
    for (int kc = 0; kc < 8; ++kc) {
      const int cc = kc*8;
      unsigned a0 = __float_as_uint(ysc[(fr0+grp)*XSS + cc + tig]);
      unsigned a1 = __float_as_uint(ysc[(fr0+grp+8)*XSS + cc + tig]);
      unsigned a2 = __float_as_uint(ysc[(fr0+grp)*XSS + cc + tig + 4]);
      unsigned a3 = __float_as_uint(ysc[(fr0+grp+8)*XSS + cc + tig + 4]);
      #pragma unroll
      for (int nt = 0; nt < 2; ++nt) {
        unsigned b0 = __float_as_uint(rwT[(cc+tig)*17 + nt*8 + grp]);
        unsigned b1 = __float_as_uint(rwT[(cc+tig+4)*17 + nt*8 + grp]);
        MMA_TF32(acc[nt], a0,a1,a2,a3, b0,b1);
      }
    }
    #pragma unroll
    for (int nt = 0; nt < 2; ++nt)
      #pragma unroll
      for (int q = 0; q < 4; ++q) {
        int frow = fr0 + grp + ((q >> 1) << 3);
        int p = nt*8 + 2*tig + (q & 1);
        if (frow < nf) {
          float v = acc[nt][q] + par[320+p];
          g_hp[(size_t)p*NFP + (size_t)n*FRP + f0 + frow] = v/(1.f+__expf(-v));
        }
      }
  }
}

// ---------------------------------------------------------------------------
// K2: per-channel GEMM  hq[n,g,p] = sum_f hp[p,n,f] * fW[p,g,f] + fB[p,g]
//     tf32 mma m16n8k8 (raw-f32 truncation), 128x64 tile, reg-prefetch 2-buf
// ---------------------------------------------------------------------------
#define K2_LOAD(FT) { \
  _Pragma("unroll") for (int j = 0; j < 4; ++j) { \
    int u = tid + j*256; int row = u >> 3, kq = u & 7; \
    int nn = n0 + row; \
    ra[j] = make_float4(0.f,0.f,0.f,0.f); \
    if (nn < NN) ra[j] = *(const float4*)&A[(size_t)nn*FRP + (FT) + kq*4]; \
  } \
  _Pragma("unroll") for (int j = 0; j < 8; ++j) { \
    int u = tid + j*256; int row = u >> 5, k = u & 31; \
    int gg = g0 + row, ff = (FT) + k; \
    rb[j] = (gg < FR && ff < FR) ? Bw[(size_t)gg*FR + ff] : 0.f; \
  } }

#define K2_STORE(BUF) { \
  _Pragma("unroll") for (int j = 0; j < 4; ++j) { \
    int u = tid + j*256; int row = u >> 3, kq = u & 7; \
    *(float4*)&As[BUF][row*36 + kq*4] = ra[j]; \
  } \
  _Pragma("unroll") for (int j = 0; j < 8; ++j) { \
    int u = tid + j*256; int row = u >> 5, k = u & 31; \
    Bs[BUF][row*36 + k] = rb[j]; \
  } }

__global__ __launch_bounds__(256) void k_fgemm(const float* __restrict__ fW,
                                               const float* __restrict__ fB)
{
  __shared__ float As[2][128*36];
  __shared__ float Bs[2][64*36];
  __shared__ float fBs[64];
  const int p  = blockIdx.z;
  const int n0 = blockIdx.x * 128, g0 = blockIdx.y * 64;
  const float* A  = g_hp + (size_t)p*NFP;      // [NN][FRP] (pad cols are 0)
  const float* Bw = fW   + (size_t)p*FR*FR;    // [FR(g)][FR(f)]
  const int tid = threadIdx.x;
  const int lane = tid & 31, wid = tid >> 5;
  const int wm = (wid & 3) * 32, wn = (wid >> 2) * 32;
  const int grp = lane >> 2, tig = lane & 3;
  if (tid < 64) fBs[tid] = (g0+tid < FR) ? fB[p*FR + g0 + tid] : 0.f;

  float acc[2][4][4];
  #pragma unroll
  for (int i = 0; i < 2; ++i)
    #pragma unroll
    for (int j = 0; j < 4; ++j)
      #pragma unroll
      for (int q = 0; q < 4; ++q) acc[i][j][q] = 0.f;

  float4 ra[4]; float rb[8];
  K2_LOAD(0)
  K2_STORE(0)
  __syncthreads();

  for (int it = 0; it < 9; ++it) {
    if (it < 8) { K2_LOAD((it+1)*32) }
    const int cur = it & 1;
    #pragma unroll
    for (int k8 = 0; k8 < 4; ++k8) {
      const int col = k8*8 + tig;
      unsigned a[2][4];
      #pragma unroll
      for (int mt = 0; mt < 2; ++mt) {
        int r = wm + mt*16 + grp;
        a[mt][0] = __float_as_uint(As[cur][r*36 + col]);
        a[mt][1] = __float_as_uint(As[cur][(r+8)*36 + col]);
        a[mt][2] = __float_as_uint(As[cur][r*36 + col + 4]);
        a[mt][3] = __float_as_uint(As[cur][(r+8)*36 + col + 4]);
      }
      #pragma unroll
      for (int nt = 0; nt < 4; ++nt) {
        int rbw = wn + nt*8 + grp;
        unsigned b0 = __float_as_uint(Bs[cur][rbw*36 + col]);
        unsigned b1 = __float_as_uint(Bs[cur][rbw*36 + col + 4]);
        #pragma unroll
        for (int mt = 0; mt < 2; ++mt)
          MMA_TF32(acc[mt][nt], a[mt][0],a[mt][1],a[mt][2],a[mt][3], b0,b1);
      }
    }
    if (it < 8) {
      K2_STORE((it+1) & 1)
      __syncthreads();
    }
  }

  #pragma unroll
  for (int mt = 0; mt < 2; ++mt) {
    #pragma unroll
    for (int nt = 0; nt < 4; ++nt) {
      int r = n0 + wm + mt*16 + grp;
      int gl = wn + nt*8 + tig*2;
      int g = g0 + gl;
      #pragma unroll
      for (int q = 0; q < 4; ++q) {
        int rr = r + (q >> 1) * 8;
        int gc = g + (q & 1);
        if (rr < NN && gc < FR)
          g_hq[((size_t)rr*FR + gc)*CPP + p] = acc[mt][nt][q] + fBs[gl + (q&1)];
      }
    }
  }
}

// ---------------------------------------------------------------------------
// K3: MMA expand + silu + residual, LN, MMA grouped conv #2, coalesced out
// ---------------------------------------------------------------------------
__global__ __launch_bounds__(256, 4) void k_freq2(
    float* __restrict__ out,
    const float* __restrict__ ew_, const float* __restrict__ eb_,
    const float* __restrict__ g2, const float* __restrict__ b2,
    const float* __restrict__ w2_, const float* __restrict__ cb2,
    const float* __restrict__ a2)
{
  extern __shared__ float sm[];
  float* xs  = sm;              // [67*68]
  float* ysb = xs + 67*XSS;     // [83*68]; hqs (80*20 tf32) aliases its start
  float* wcg = ysb + 83*XSS;    // [8g][3kk][8c'][9] tf32 conv weights
  float* ewt = wcg + 8*3*8*9;   // [64*17]  tf32 [c][p]
  float* par = ewt + 64*17;     // eb|g2|b2|cb2 (64 each)
  float* ysc = ysb + XSS;
  float* hqs = ysb;             // aliased: dead once LN phase starts

  const int tid = threadIdx.x;
  const int n = blockIdx.x;
  const int b = n / TT, t = n % TT;
  const int f0 = blockIdx.y * CH;
  const int f1 = min(FR, f0 + CH);
  const int nf = f1 - f0;
  const int e0 = (f0 > 0) ? f0 - 1 : 0;
  const int e1 = (f1 < FR) ? f1 + 1 : FR;
  const int ne = e1 - e0;
  const int off = (f0 > 0) ? 1 : 0;

  if (tid < CC) {
    par[tid] = eb_[tid]; par[64+tid] = g2[tid];
    par[128+tid] = b2[tid]; par[192+tid] = cb2[tid];
  }
  for (int i = tid; i < 8*3*64; i += 256) {
    int g = i / 192, r = i % 192, kk = r >> 6, s = r & 63;
    int cp = s >> 3, ci = s & 7;
    wcg[((g*3+kk)*8 + cp)*9 + ci] = to_tf32(w2_[(g*8+cp)*24 + ci*3 + kk]);
  }
  for (int i = tid; i < CC*CPP; i += 256) {
    int c = i >> 4, p = i & 15;
    ewt[c*17 + p] = to_tf32(ew_[c*CPP + p]);
  }
  const float alpha = __ldg(a2);
  const float4* x1src = (const float4*)(g_x1 + ((size_t)n*FR + e0)*CC);
  for (int i = tid; i < ne*16; i += 256) {
    int r = i >> 4, q = i & 15;
    *(float4*)(xs + r*XSS + q*4) = x1src[i];
  }
  const float4* hqsrc = (const float4*)(g_hq + ((size_t)n*FR + e0)*CPP);
  for (int i = tid; i < ne*4; i += 256) {
    int r = i >> 2, q = i & 3;
    float4 v = hqsrc[i];
    v.x = to_tf32(v.x); v.y = to_tf32(v.y); v.z = to_tf32(v.z); v.w = to_tf32(v.w);
    *(float4*)(hqs + r*20 + q*4) = v;
  }
  __syncthreads();

  const int wid = tid >> 5, lane = tid & 31;
  const int grp = lane >> 2, tig = lane & 3;

  // MMA expand: warp w = c-tile w*8, 5 f-tiles of 16; then silu + residual
  {
    float acc[5][4];
    #pragma unroll
    for (int mt = 0; mt < 5; ++mt)
      #pragma unroll
      for (int q = 0; q < 4; ++q) acc[mt][q] = 0.f;
    #pragma unroll
    for (int kc = 0; kc < 2; ++kc) {
      unsigned b0 = __float_as_uint(ewt[(wid*8+grp)*17 + kc*8 + tig]);
      unsigned b1 = __float_as_uint(ewt[(wid*8+grp)*17 + kc*8 + tig + 4]);
      #pragma unroll
      for (int mt = 0; mt < 5; ++mt) {
        unsigned a0 = __float_as_uint(hqs[(mt*16+grp)*20 + kc*8 + tig]);
        unsigned a1 = __float_as_uint(hqs[(mt*16+grp+8)*20 + kc*8 + tig]);
        unsigned a2 = __float_as_uint(hqs[(mt*16+grp)*20 + kc*8 + tig + 4]);
        unsigned a3 = __float_as_uint(hqs[(mt*16+grp+8)*20 + kc*8 + tig + 4]);
        MMA_TF32(acc[mt], a0,a1,a2,a3, b0,b1);
      }
    }
    __syncthreads();   // all hqs reads complete before xs update / ysb reuse
    #pragma unroll
    for (int mt = 0; mt < 5; ++mt)
      #pragma unroll
      for (int q = 0; q < 4; ++q) {
        int f = mt*16 + grp + ((q >> 1) << 3);
        int c = wid*8 + 2*tig + (q & 1);
        if (f < ne) {
          float v = acc[mt][q] + par[c];
          xs[f*XSS+c] += v/(1.f+__expf(-v));
        }
      }
  }
  __syncthreads();

  // LN over all ne rows -> ysc (tf32); zero conv halo rows (ysb now free)
  for (int i = tid; i < XSS; i += 256) ysb[i] = 0.f;
  for (int i = tid + (ne+1)*XSS; i < 83*XSS; i += 256) ysb[i] = 0.f;
  for (int r = wid; r < ne; r += 8) {
    float v0 = xs[r*XSS+lane], v1 = xs[r*XSS+lane+32];
    float s = v0+v1, q = v0*v0+v1*v1;
    WRED2(s,q)
    float m = s*(1.f/64.f);
    float rr = rsqrtf(fmaxf(q*(1.f/64.f)-m*m, 0.f)+LN_EPS);
    ysc[r*XSS+lane]    = to_tf32((v0-m)*rr*par[64+lane] + par[128+lane]);
    ysc[r*XSS+lane+32] = to_tf32((v1-m)*rr*par[96+lane] + par[160+lane]);
  }
  __syncthreads();

  // MMA grouped conv #2 + leaky + residual -> xs
  CONV_MMA(192, {
    int xr = fl + off;
    xs[xr*XSS + c] += lv;
  })
  __syncthreads();

  // coalesced copy xs rows [off, off+nf) -> out rows [f0, f1)
  float* obase = out + ((size_t)b*FR*TT + t)*CC;
  for (int i = tid; i < nf*16; i += 256) {
    int r = i >> 4, q = i & 15;
    *(float4*)(obase + (size_t)(f0+r)*TT*CC + q*4) =
        *(const float4*)(xs + (r+off)*XSS + q*4);
  }
}

// ---------------------------------------------------------------------------
extern "C" void kernel_launch(void* const* d_in, const int* in_sizes, int n_in,
                              void* d_out, int out_size)
{
  const float* h     = (const float*)d_in[0];
  const float* fc1g  = (const float*)d_in[1];
  const float* fc1b  = (const float*)d_in[2];
  const float* fc1w  = (const float*)d_in[3];
  const float* fc1cb = (const float*)d_in[4];
  const float* fc1a  = (const float*)d_in[5];
  const float* fblg  = (const float*)d_in[6];
  const float* fblb  = (const float*)d_in[7];
  const float* redw  = (const float*)d_in[8];
  const float* redb  = (const float*)d_in[9];
  const float* fW    = (const float*)d_in[10];
  const float* fB    = (const float*)d_in[11];
  const float* expw  = (const float*)d_in[12];
  const float* expb  = (const float*)d_in[13];
  const float* fc2g  = (const float*)d_in[14];
  const float* fc2b  = (const float*)d_in[15];
  const float* fc2w  = (const float*)d_in[16];
  const float* fc2cb = (const float*)d_in[17];
  const float* fc2a  = (const float*)d_in[18];
  float* out = (float*)d_out;

  const int SM1 = (67*XSS + 83*XSS + 8*3*8*9 + 64*17 + 336) * 4;
  const int SM3 = (67*XSS + 83*XSS + 8*3*8*9 + 64*17 + 256) * 4;
  cudaFuncSetAttribute(k_freq1, cudaFuncAttributeMaxDynamicSharedMemorySize, SM1);
  cudaFuncSetAttribute(k_freq2, cudaFuncAttributeMaxDynamicSharedMemorySize, SM3);

  dim3 g1(NN, 4);
  k_freq1<<<g1, 256, SM1>>>(h, fc1g, fc1b, fc1w, fc1cb, fc1a,
                            fblg, fblb, redw, redb);
  dim3 gg((NN+127)/128, (FR+63)/64, CPP);
  k_fgemm<<<gg, 256>>>(fW, fB);
  dim3 g3(NN, 4);
  k_freq2<<<g3, 256, SM3>>>(out, expw, expb, fc2g, fc2b, fc2w, fc2cb, fc2a);
}